// round 1
// baseline (speedup 1.0000x reference)
#include <cuda_runtime.h>
#include <math.h>

// ---------------------------------------------------------------------------
// DotProductAttention: O = softmax((XqWq+bq)(XkWk+bk)^T / sqrt(1024)) (XvWv+bv)
// B=4, S=2048, MODEL=DK=DV=1024
// Round-1 baseline: fp32 FFMA tiled GEMMs (correctness anchor), 4-stage pipeline
// ---------------------------------------------------------------------------

#define BATCH 4
#define SEQ   2048
#define MODEL 1024
#define MTOT  (BATCH * SEQ)   // 8192

#define BM 64
#define BN 64
#define BK 16
#define TM 4
#define TN 4
// threads: 16x16 = 256

// __device__ scratch (allocation-free per harness rules)
__device__ float g_Q[MTOT * MODEL];
__device__ float g_K[MTOT * MODEL];
__device__ float g_V[MTOT * MODEL];
__device__ float g_S[(size_t)BATCH * SEQ * SEQ];

// C[M,N] = A[M,K] @ B[K,N] + bias   (bias may be null), batched over z
__global__ void gemm_nn(const float* __restrict__ A, const float* __restrict__ B,
                        const float* __restrict__ bias, float* __restrict__ C,
                        int M, int N, int K,
                        long sA, long sB, long sC) {
    A += (long)blockIdx.z * sA;
    B += (long)blockIdx.z * sB;
    C += (long)blockIdx.z * sC;

    __shared__ float As[BK][BM + 4];
    __shared__ float Bs[BK][BN];

    const int tx = threadIdx.x, ty = threadIdx.y;
    const int tid = ty * 16 + tx;
    const int rowBase = blockIdx.y * BM;
    const int colBase = blockIdx.x * BN;

    // A tile: 64 rows x 16 cols, one float4 per thread (along k)
    const int aRow = tid / 4;            // 0..63
    const int aCol = (tid % 4) * 4;      // 0,4,8,12
    // B tile: 16 rows x 64 cols, one float4 per thread (along n)
    const int bRow = tid / 16;           // 0..15
    const int bCol = (tid % 16) * 4;     // 0..60

    float acc[TM][TN];
#pragma unroll
    for (int i = 0; i < TM; i++)
#pragma unroll
        for (int j = 0; j < TN; j++) acc[i][j] = 0.0f;

    for (int kt = 0; kt < K; kt += BK) {
        float4 av = *(const float4*)&A[(long)(rowBase + aRow) * K + kt + aCol];
        As[aCol + 0][aRow] = av.x;
        As[aCol + 1][aRow] = av.y;
        As[aCol + 2][aRow] = av.z;
        As[aCol + 3][aRow] = av.w;

        float4 bv = *(const float4*)&B[(long)(kt + bRow) * N + colBase + bCol];
        *(float4*)&Bs[bRow][bCol] = bv;

        __syncthreads();

#pragma unroll
        for (int k = 0; k < BK; k++) {
            float a[TM], b[TN];
#pragma unroll
            for (int i = 0; i < TM; i++) a[i] = As[k][ty * TM + i];
#pragma unroll
            for (int j = 0; j < TN; j++) b[j] = Bs[k][tx * TN + j];
#pragma unroll
            for (int i = 0; i < TM; i++)
#pragma unroll
                for (int j = 0; j < TN; j++) acc[i][j] = fmaf(a[i], b[j], acc[i][j]);
        }
        __syncthreads();
    }

#pragma unroll
    for (int i = 0; i < TM; i++) {
        const int r = rowBase + ty * TM + i;
#pragma unroll
        for (int j = 0; j < TN; j++) {
            const int c = colBase + tx * TN + j;
            float v = acc[i][j];
            if (bias) v += bias[c];
            C[(long)r * N + c] = v;
        }
    }
}

// C[M,N] = scale * (A[M,K] @ B[N,K]^T), batched over z
__global__ void gemm_nt_scaled(const float* __restrict__ A, const float* __restrict__ B,
                               float* __restrict__ C,
                               int M, int N, int K,
                               long sA, long sB, long sC, float scale) {
    A += (long)blockIdx.z * sA;
    B += (long)blockIdx.z * sB;
    C += (long)blockIdx.z * sC;

    __shared__ float As[BK][BM + 4];
    __shared__ float Bs[BK][BN + 4];

    const int tx = threadIdx.x, ty = threadIdx.y;
    const int tid = ty * 16 + tx;
    const int rowBase = blockIdx.y * BM;
    const int colBase = blockIdx.x * BN;

    const int aRow = tid / 4;
    const int aCol = (tid % 4) * 4;

    float acc[TM][TN];
#pragma unroll
    for (int i = 0; i < TM; i++)
#pragma unroll
        for (int j = 0; j < TN; j++) acc[i][j] = 0.0f;

    for (int kt = 0; kt < K; kt += BK) {
        float4 av = *(const float4*)&A[(long)(rowBase + aRow) * K + kt + aCol];
        As[aCol + 0][aRow] = av.x;
        As[aCol + 1][aRow] = av.y;
        As[aCol + 2][aRow] = av.z;
        As[aCol + 3][aRow] = av.w;

        // B tile: 64 n-rows x 16 k-cols (same shape as A tile)
        float4 bv = *(const float4*)&B[(long)(colBase + aRow) * K + kt + aCol];
        Bs[aCol + 0][aRow] = bv.x;
        Bs[aCol + 1][aRow] = bv.y;
        Bs[aCol + 2][aRow] = bv.z;
        Bs[aCol + 3][aRow] = bv.w;

        __syncthreads();

#pragma unroll
        for (int k = 0; k < BK; k++) {
            float a[TM], b[TN];
#pragma unroll
            for (int i = 0; i < TM; i++) a[i] = As[k][ty * TM + i];
#pragma unroll
            for (int j = 0; j < TN; j++) b[j] = Bs[k][tx * TN + j];
#pragma unroll
            for (int i = 0; i < TM; i++)
#pragma unroll
                for (int j = 0; j < TN; j++) acc[i][j] = fmaf(a[i], b[j], acc[i][j]);
        }
        __syncthreads();
    }

#pragma unroll
    for (int i = 0; i < TM; i++) {
        const int r = rowBase + ty * TM + i;
#pragma unroll
        for (int j = 0; j < TN; j++) {
            const int c = colBase + tx * TN + j;
            C[(long)r * N + c] = acc[i][j] * scale;
        }
    }
}

// Row-wise softmax over ncols, one block (256 thr) per row
__global__ void softmax_rows(float* __restrict__ S, int ncols) {
    float* row = S + (size_t)blockIdx.x * ncols;
    const int tid = threadIdx.x;
    __shared__ float red[8];

    float m = -3.402823466e38f;
    for (int c = tid; c < ncols; c += 256) m = fmaxf(m, row[c]);
#pragma unroll
    for (int o = 16; o > 0; o >>= 1) m = fmaxf(m, __shfl_xor_sync(0xffffffffu, m, o));
    if ((tid & 31) == 0) red[tid >> 5] = m;
    __syncthreads();
    m = red[0];
#pragma unroll
    for (int i = 1; i < 8; i++) m = fmaxf(m, red[i]);

    float s = 0.0f;
    for (int c = tid; c < ncols; c += 256) {
        float e = expf(row[c] - m);
        row[c] = e;
        s += e;
    }
#pragma unroll
    for (int o = 16; o > 0; o >>= 1) s += __shfl_xor_sync(0xffffffffu, s, o);
    __syncthreads();   // red[] reuse
    if ((tid & 31) == 0) red[tid >> 5] = s;
    __syncthreads();
    s = 0.0f;
#pragma unroll
    for (int i = 0; i < 8; i++) s += red[i];
    const float inv = 1.0f / s;
    for (int c = tid; c < ncols; c += 256) row[c] *= inv;
}

extern "C" void kernel_launch(void* const* d_in, const int* in_sizes, int n_in,
                              void* d_out, int out_size) {
    const float* q  = (const float*)d_in[0];
    const float* k  = (const float*)d_in[1];
    const float* v  = (const float*)d_in[2];
    const float* Wq = (const float*)d_in[3];
    const float* Wk = (const float*)d_in[4];
    const float* Wv = (const float*)d_in[5];
    const float* bq = (const float*)d_in[6];
    const float* bk = (const float*)d_in[7];
    const float* bv = (const float*)d_in[8];
    float* out = (float*)d_out;

    float *Qp, *Kp, *Vp, *Sp;
    cudaGetSymbolAddress((void**)&Qp, g_Q);
    cudaGetSymbolAddress((void**)&Kp, g_K);
    cudaGetSymbolAddress((void**)&Vp, g_V);
    cudaGetSymbolAddress((void**)&Sp, g_S);

    dim3 thr(16, 16);

    // 1) Projections: [8192,1024] @ [1024,1024] + bias
    dim3 gproj(MODEL / BN, MTOT / BM, 1);
    gemm_nn<<<gproj, thr>>>(q, Wq, bq, Qp, MTOT, MODEL, MODEL, 0, 0, 0);
    gemm_nn<<<gproj, thr>>>(k, Wk, bk, Kp, MTOT, MODEL, MODEL, 0, 0, 0);
    gemm_nn<<<gproj, thr>>>(v, Wv, bv, Vp, MTOT, MODEL, MODEL, 0, 0, 0);

    // 2) Scores: S[b] = Q[b] @ K[b]^T * (1/sqrt(1024))
    dim3 gsc(SEQ / BN, SEQ / BM, BATCH);
    gemm_nt_scaled<<<gsc, thr>>>(Qp, Kp, Sp, SEQ, SEQ, MODEL,
                                 (long)SEQ * MODEL, (long)SEQ * MODEL,
                                 (long)SEQ * SEQ, 0.03125f);

    // 3) Softmax over last dim
    softmax_rows<<<BATCH * SEQ, 256>>>(Sp, SEQ);

    // 4) O[b] = P[b] @ V[b]
    dim3 gpv(MODEL / BN, SEQ / BM, BATCH);
    gemm_nn<<<gpv, thr>>>(Sp, Vp, nullptr, out, SEQ, MODEL, SEQ,
                          (long)SEQ * SEQ, (long)SEQ * MODEL, (long)SEQ * MODEL);
}

// round 3
// speedup vs baseline: 1.4604x; 1.4604x over previous
#include <cuda_runtime.h>
#include <cstdint>
#include <math.h>

// ---------------------------------------------------------------------------
// DotProductAttention on GB300 (compiled as plain sm_103 -> use mma.sync).
// O = softmax((qWq+bq)(kWk+bk)^T / 32) (vWv+bv);  B=4, S=2048, D=1024
// GEMM core: m16n8k8 tf32 mma.sync, 3xTF32 split for fp32-level accuracy.
// ---------------------------------------------------------------------------

#define BATCH 4
#define SEQ   2048
#define MODEL 1024
#define MTOT  (BATCH * SEQ)   // 8192

// scratch (allocation-free)
__device__ float g_Q [MTOT * MODEL];
__device__ float g_K [MTOT * MODEL];
__device__ float g_V [MTOT * MODEL];
__device__ float g_Vt[MTOT * MODEL];
__device__ float g_S [(size_t)BATCH * SEQ * SEQ];
__device__ float g_Wt[MODEL * MODEL];

// ------------------------------- GEMM config -------------------------------
#define BM 128
#define BN 128
#define BK 32
#define NTHREADS 256
// smem regions (in uint32 elements). A: 8 m-tiles x 4 k-slices, block=132.
// B: 16 n-tiles x 4 k-slices, block=66.
#define A_BLK 132
#define B_BLK 66
#define OFF_AHI 0
#define OFF_ALO (OFF_AHI + 32 * A_BLK)   // 4224
#define OFF_BHI (OFF_ALO + 32 * A_BLK)   // 8448
#define OFF_BLO (OFF_BHI + 64 * B_BLK)   // 12672
#define SMEM_U32 (OFF_BLO + 64 * B_BLK)  // 16896 -> 67584 bytes
#define SMEM_BYTES (SMEM_U32 * 4)

__device__ __forceinline__ void tf32_split(float v, uint32_t& hi, uint32_t& lo) {
    asm("cvt.rna.tf32.f32 %0, %1;" : "=r"(hi) : "f"(v));
    float l = v - __uint_as_float(hi);
    asm("cvt.rna.tf32.f32 %0, %1;" : "=r"(lo) : "f"(l));
}

__device__ __forceinline__ void mma_tf32(float* c, const uint32_t* a, const uint32_t* b) {
    asm volatile(
        "mma.sync.aligned.m16n8k8.row.col.f32.tf32.tf32.f32 "
        "{%0,%1,%2,%3}, {%4,%5,%6,%7}, {%8,%9}, {%0,%1,%2,%3};"
        : "+f"(c[0]), "+f"(c[1]), "+f"(c[2]), "+f"(c[3])
        : "r"(a[0]), "r"(a[1]), "r"(a[2]), "r"(a[3]), "r"(b[0]), "r"(b[1]));
}

// C[M,N] = scale * (A[M,K] @ B[N,K]^T) + bias; A,B K-major; batched over z.
__global__ void __launch_bounds__(NTHREADS, 2) gemm_tf32_3x(
    const float* __restrict__ A, int lda,
    const float* __restrict__ B, int ldb,
    float* __restrict__ C, int ldc,
    const float* __restrict__ bias, float scale, int K,
    long long sA, long long sB, long long sC)
{
    extern __shared__ uint32_t sm[];
    const int tid = threadIdx.x;
    const int wid = tid >> 5, lane = tid & 31;
    const int warpM = wid & 3;    // 4 row-bands of 32
    const int warpN = wid >> 2;   // 2 col-bands of 64

    A += (long long)blockIdx.z * sA;
    B += (long long)blockIdx.z * sB;
    C += (long long)blockIdx.z * sC;
    const int rowBase = blockIdx.y * BM;
    const int colBase = blockIdx.x * BN;

    float acc[2][8][4];
#pragma unroll
    for (int mt = 0; mt < 2; mt++)
#pragma unroll
        for (int nt = 0; nt < 8; nt++)
#pragma unroll
            for (int e = 0; e < 4; e++) acc[mt][nt][e] = 0.0f;

    for (int kt = 0; kt < K; kt += BK) {
        // ---- stage A: 128 rows x 32 cols (1024 float4, 4 per thread) ----
#pragma unroll
        for (int j = 0; j < 4; j++) {
            const int f4 = j * 256 + tid;
            const int r = f4 >> 3, qc = f4 & 7;
            const float4 v = *(const float4*)(A + (size_t)(rowBase + r) * lda + kt + qc * 4);
            const int mt = r >> 4, rr = r & 15;
            const int ks = qc >> 1;
            const int reg = (rr >> 3) + ((qc & 1) << 1);
            uint32_t* dh = sm + OFF_AHI + (mt * 4 + ks) * A_BLK + (rr & 7) * 16 + reg;
            uint32_t* dl = sm + OFF_ALO + (mt * 4 + ks) * A_BLK + (rr & 7) * 16 + reg;
            float vv[4] = {v.x, v.y, v.z, v.w};
#pragma unroll
            for (int e = 0; e < 4; e++) {
                uint32_t hi, lo;
                tf32_split(vv[e], hi, lo);
                dh[e * 4] = hi;
                dl[e * 4] = lo;
            }
        }
        // ---- stage B: 128 n-rows x 32 k-cols ----
#pragma unroll
        for (int j = 0; j < 4; j++) {
            const int f4 = j * 256 + tid;
            const int rn = f4 >> 3, qc = f4 & 7;
            const float4 v = *(const float4*)(B + (size_t)(colBase + rn) * ldb + kt + qc * 4);
            const int nt = rn >> 3, nn = rn & 7;
            const int ks = qc >> 1;
            const int reg = qc & 1;
            uint32_t* dh = sm + OFF_BHI + (nt * 4 + ks) * B_BLK + nn * 8 + reg;
            uint32_t* dl = sm + OFF_BLO + (nt * 4 + ks) * B_BLK + nn * 8 + reg;
            float vv[4] = {v.x, v.y, v.z, v.w};
#pragma unroll
            for (int e = 0; e < 4; e++) {
                uint32_t hi, lo;
                tf32_split(vv[e], hi, lo);
                dh[e * 2] = hi;
                dl[e * 2] = lo;
            }
        }
        __syncthreads();

        // ---- compute: 4 k-slices x 3 tf32 passes ----
#pragma unroll
        for (int ks = 0; ks < 4; ks++) {
            uint32_t aHi[2][4], aLo[2][4], bHi[8][2], bLo[8][2];
#pragma unroll
            for (int mt = 0; mt < 2; mt++) {
                const int blk = ((warpM * 2 + mt) * 4 + ks) * A_BLK + lane * 4;
                *(uint4*)aHi[mt] = *(const uint4*)(sm + OFF_AHI + blk);
                *(uint4*)aLo[mt] = *(const uint4*)(sm + OFF_ALO + blk);
            }
#pragma unroll
            for (int nt = 0; nt < 8; nt++) {
                const int blk = ((warpN * 8 + nt) * 4 + ks) * B_BLK + lane * 2;
                *(uint2*)bHi[nt] = *(const uint2*)(sm + OFF_BHI + blk);
                *(uint2*)bLo[nt] = *(const uint2*)(sm + OFF_BLO + blk);
            }
#pragma unroll
            for (int mt = 0; mt < 2; mt++)
#pragma unroll
                for (int nt = 0; nt < 8; nt++) {
                    mma_tf32(acc[mt][nt], aHi[mt], bHi[nt]);
                    mma_tf32(acc[mt][nt], aHi[mt], bLo[nt]);
                    mma_tf32(acc[mt][nt], aLo[mt], bHi[nt]);
                }
        }
        __syncthreads();
    }

    // ---- epilogue ----
    const int gID = lane >> 2, tig = lane & 3;
#pragma unroll
    for (int mt = 0; mt < 2; mt++) {
        const int r0 = rowBase + warpM * 32 + mt * 16 + gID;
#pragma unroll
        for (int nt = 0; nt < 8; nt++) {
            const int col = colBase + warpN * 64 + nt * 8 + tig * 2;
            float b0 = bias ? bias[col] : 0.f;
            float b1 = bias ? bias[col + 1] : 0.f;
            float2 o0 = {acc[mt][nt][0] * scale + b0, acc[mt][nt][1] * scale + b1};
            float2 o1 = {acc[mt][nt][2] * scale + b0, acc[mt][nt][3] * scale + b1};
            *(float2*)(C + (size_t)r0 * ldc + col) = o0;
            *(float2*)(C + (size_t)(r0 + 8) * ldc + col) = o1;
        }
    }
}

// ------------------------- transpose (K-major prep) ------------------------
__global__ void transpose_k(const float* __restrict__ in, float* __restrict__ out,
                            int R, int C, long long sIn, long long sOut) {
    __shared__ float t[32][33];
    in  += (long long)blockIdx.z * sIn;
    out += (long long)blockIdx.z * sOut;
    const int c0 = blockIdx.x * 32, r0 = blockIdx.y * 32;
#pragma unroll
    for (int i = 0; i < 4; i++)
        t[threadIdx.y + i * 8][threadIdx.x] =
            in[(size_t)(r0 + threadIdx.y + i * 8) * C + c0 + threadIdx.x];
    __syncthreads();
#pragma unroll
    for (int i = 0; i < 4; i++)
        out[(size_t)(c0 + threadIdx.y + i * 8) * R + r0 + threadIdx.x] =
            t[threadIdx.x][threadIdx.y + i * 8];
}

// ------------------------------- softmax -----------------------------------
__global__ void softmax_rows(float* __restrict__ S, int ncols) {
    float* row = S + (size_t)blockIdx.x * ncols;
    const int tid = threadIdx.x;
    __shared__ float red[8];

    float m = -3.402823466e38f;
    for (int c = tid; c < ncols; c += 256) m = fmaxf(m, row[c]);
#pragma unroll
    for (int o = 16; o > 0; o >>= 1) m = fmaxf(m, __shfl_xor_sync(0xffffffffu, m, o));
    if ((tid & 31) == 0) red[tid >> 5] = m;
    __syncthreads();
    m = red[0];
#pragma unroll
    for (int i = 1; i < 8; i++) m = fmaxf(m, red[i]);

    float s = 0.0f;
    for (int c = tid; c < ncols; c += 256) {
        float e = expf(row[c] - m);
        row[c] = e;
        s += e;
    }
#pragma unroll
    for (int o = 16; o > 0; o >>= 1) s += __shfl_xor_sync(0xffffffffu, s, o);
    __syncthreads();
    if ((tid & 31) == 0) red[tid >> 5] = s;
    __syncthreads();
    s = 0.0f;
#pragma unroll
    for (int i = 0; i < 8; i++) s += red[i];
    const float inv = 1.0f / s;
    for (int c = tid; c < ncols; c += 256) row[c] *= inv;
}

// ------------------------------- launcher ----------------------------------
extern "C" void kernel_launch(void* const* d_in, const int* in_sizes, int n_in,
                              void* d_out, int out_size) {
    const float* q  = (const float*)d_in[0];
    const float* k  = (const float*)d_in[1];
    const float* v  = (const float*)d_in[2];
    const float* Wq = (const float*)d_in[3];
    const float* Wk = (const float*)d_in[4];
    const float* Wv = (const float*)d_in[5];
    const float* bq = (const float*)d_in[6];
    const float* bk = (const float*)d_in[7];
    const float* bv = (const float*)d_in[8];
    float* out = (float*)d_out;

    float *Qp, *Kp, *Vp, *Vtp, *Sp, *Wtp;
    cudaGetSymbolAddress((void**)&Qp,  g_Q);
    cudaGetSymbolAddress((void**)&Kp,  g_K);
    cudaGetSymbolAddress((void**)&Vp,  g_V);
    cudaGetSymbolAddress((void**)&Vtp, g_Vt);
    cudaGetSymbolAddress((void**)&Sp,  g_S);
    cudaGetSymbolAddress((void**)&Wtp, g_Wt);

    static int smem_set = 0;
    if (!smem_set) {
        cudaFuncSetAttribute(gemm_tf32_3x, cudaFuncAttributeMaxDynamicSharedMemorySize, SMEM_BYTES);
        smem_set = 1;
    }

    const dim3 tthr(32, 8);

    // 1) projections: C = X @ W + b  (Wt = W^T, K-major)
    dim3 gproj(MODEL / BN, MTOT / BM, 1);           // (8, 64)
    transpose_k<<<dim3(32, 32, 1), tthr>>>(Wq, Wtp, MODEL, MODEL, 0, 0);
    gemm_tf32_3x<<<gproj, NTHREADS, SMEM_BYTES>>>(q, MODEL, Wtp, MODEL, Qp, MODEL, bq, 1.0f, MODEL, 0, 0, 0);
    transpose_k<<<dim3(32, 32, 1), tthr>>>(Wk, Wtp, MODEL, MODEL, 0, 0);
    gemm_tf32_3x<<<gproj, NTHREADS, SMEM_BYTES>>>(k, MODEL, Wtp, MODEL, Kp, MODEL, bk, 1.0f, MODEL, 0, 0, 0);
    transpose_k<<<dim3(32, 32, 1), tthr>>>(Wv, Wtp, MODEL, MODEL, 0, 0);
    gemm_tf32_3x<<<gproj, NTHREADS, SMEM_BYTES>>>(v, MODEL, Wtp, MODEL, Vp, MODEL, bv, 1.0f, MODEL, 0, 0, 0);

    // 2) scores: S[b] = (Q[b] @ K[b]^T) / 32
    dim3 gsc(SEQ / BN, SEQ / BM, BATCH);            // (16, 16, 4)
    gemm_tf32_3x<<<gsc, NTHREADS, SMEM_BYTES>>>(Qp, MODEL, Kp, MODEL, Sp, SEQ, nullptr, 0.03125f,
                                                MODEL, (long long)SEQ * MODEL, (long long)SEQ * MODEL,
                                                (long long)SEQ * SEQ);

    // 3) softmax rows
    softmax_rows<<<BATCH * SEQ, 256>>>(Sp, SEQ);

    // 4) Vt[b] = V[b]^T
    transpose_k<<<dim3(MODEL / 32, SEQ / 32, BATCH), tthr>>>(Vp, Vtp, SEQ, MODEL,
                                                             (long long)SEQ * MODEL,
                                                             (long long)SEQ * MODEL);

    // 5) O[b] = P[b] @ Vt[b]^T
    dim3 gpv(MODEL / BN, SEQ / BM, BATCH);          // (8, 16, 4)
    gemm_tf32_3x<<<gpv, NTHREADS, SMEM_BYTES>>>(Sp, SEQ, Vtp, SEQ, out, MODEL, nullptr, 1.0f,
                                                SEQ, (long long)SEQ * SEQ, (long long)SEQ * MODEL,
                                                (long long)SEQ * MODEL);
}

// round 4
// speedup vs baseline: 1.7748x; 1.2153x over previous
#include <cuda_runtime.h>
#include <cstdint>
#include <math.h>

// ---------------------------------------------------------------------------
// DotProductAttention (sm_103 plain target -> mma.sync m16n8k8 tf32).
// 3xTF32 for Q/K proj + scores (exp-amplified), 1-pass tf32 for V proj + PV.
// Double-buffered smem pipeline, store-side hi/lo split, fragment-linear.
// ---------------------------------------------------------------------------

#define BATCH 4
#define SEQ   2048
#define MODEL 1024
#define MTOT  (BATCH * SEQ)   // 8192

__device__ float g_Q [MTOT * MODEL];
__device__ float g_K [MTOT * MODEL];
__device__ float g_V [MTOT * MODEL];
__device__ float g_Vt[MTOT * MODEL];
__device__ float g_S [(size_t)BATCH * SEQ * SEQ];
__device__ float g_Wt[MODEL * MODEL];

// ------------------------------- GEMM config -------------------------------
#define BM 128
#define BN 128
#define BK 16
#define NTHREADS 256
#define A_BLK 132          // 128 payload + pad (u32)
#define B_BLK 66           // 64 payload + pad
// per-stage u32 offsets
#define OFF_AHI 0
#define OFF_ALO 2112       // 16 blocks * 132
#define OFF_BHI 4224
#define OFF_BLO 6336       // + 32 blocks * 66
#define STG_U32 8448
#define SMEM_BYTES (2 * STG_U32 * 4)   // 67584

__device__ __forceinline__ void tf32_split(float v, uint32_t& hi, uint32_t& lo) {
    asm("cvt.rna.tf32.f32 %0, %1;" : "=r"(hi) : "f"(v));
    float l = v - __uint_as_float(hi);
    asm("cvt.rna.tf32.f32 %0, %1;" : "=r"(lo) : "f"(l));
}
__device__ __forceinline__ uint32_t tf32_of(float v) {
    uint32_t r;
    asm("cvt.rna.tf32.f32 %0, %1;" : "=r"(r) : "f"(v));
    return r;
}
__device__ __forceinline__ void mma_tf32(float* c, const uint32_t* a, const uint32_t* b) {
    asm volatile(
        "mma.sync.aligned.m16n8k8.row.col.f32.tf32.tf32.f32 "
        "{%0,%1,%2,%3}, {%4,%5,%6,%7}, {%8,%9}, {%0,%1,%2,%3};"
        : "+f"(c[0]), "+f"(c[1]), "+f"(c[2]), "+f"(c[3])
        : "r"(a[0]), "r"(a[1]), "r"(a[2]), "r"(a[3]), "r"(b[0]), "r"(b[1]));
}

// C[M,N] = scale * (A[M,K] @ B[N,K]^T) + bias; A,B K-major; batched over z.
template <int PASSES>
__global__ void __launch_bounds__(NTHREADS, 2) gemm_tf32(
    const float* __restrict__ A, int lda,
    const float* __restrict__ B, int ldb,
    float* __restrict__ C, int ldc,
    const float* __restrict__ bias, float scale, int K,
    long long sA, long long sB, long long sC)
{
    extern __shared__ uint32_t sm[];
    const int tid = threadIdx.x;
    const int wid = tid >> 5, lane = tid & 31;
    const int warpM = wid & 3;    // 4 row-bands of 32
    const int warpN = wid >> 2;   // 2 col-bands of 64

    A += (long long)blockIdx.z * sA;
    B += (long long)blockIdx.z * sB;
    C += (long long)blockIdx.z * sC;
    const int rowBase = blockIdx.y * BM;
    const int colBase = blockIdx.x * BN;

    // staging thread mapping (2 float4 per matrix per thread)
    const int f40 = tid, f41 = 256 + tid;
    const int rA0 = f40 >> 2, cA0 = f40 & 3;
    const int rA1 = f41 >> 2, cA1 = f41 & 3;

    float4 pfA0, pfA1, pfB0, pfB1;

    auto ldg = [&](int kt) {
        pfA0 = *(const float4*)(A + (size_t)(rowBase + rA0) * lda + kt + cA0 * 4);
        pfA1 = *(const float4*)(A + (size_t)(rowBase + rA1) * lda + kt + cA1 * 4);
        pfB0 = *(const float4*)(B + (size_t)(colBase + rA0) * ldb + kt + cA0 * 4);
        pfB1 = *(const float4*)(B + (size_t)(colBase + rA1) * ldb + kt + cA1 * 4);
    };

    auto store_stage = [&](int stg) {
        uint32_t* base = sm + stg * STG_U32;
        // A: fragment-linear. block (mt*2+ks), pos = (rr&7)*16 + reg + e*4
        const float4 av[2] = {pfA0, pfA1};
        const int rAs[2] = {rA0, rA1}, cAs[2] = {cA0, cA1};
#pragma unroll
        for (int j = 0; j < 2; j++) {
            const int r = rAs[j], qc = cAs[j];
            const int mt = r >> 4, rr = r & 15, ks = qc >> 1;
            const int reg = (rr >> 3) + ((qc & 1) << 1);
            uint32_t* dh = base + OFF_AHI + (mt * 2 + ks) * A_BLK + (rr & 7) * 16 + reg;
            uint32_t* dl = base + OFF_ALO + (mt * 2 + ks) * A_BLK + (rr & 7) * 16 + reg;
            const float vv[4] = {av[j].x, av[j].y, av[j].z, av[j].w};
#pragma unroll
            for (int e = 0; e < 4; e++) {
                if (PASSES == 3) {
                    uint32_t hi, lo;
                    tf32_split(vv[e], hi, lo);
                    dh[e * 4] = hi;
                    dl[e * 4] = lo;
                } else {
                    dh[e * 4] = tf32_of(vv[e]);
                }
            }
        }
        // B: block (nt*2+ks), pos = nn*8 + (qc&1) + e*2
        const float4 bv[2] = {pfB0, pfB1};
#pragma unroll
        for (int j = 0; j < 2; j++) {
            const int rn = rAs[j], qc = cAs[j];
            const int nt = rn >> 3, nn = rn & 7, ks = qc >> 1;
            uint32_t* dh = base + OFF_BHI + (nt * 2 + ks) * B_BLK + nn * 8 + (qc & 1);
            uint32_t* dl = base + OFF_BLO + (nt * 2 + ks) * B_BLK + nn * 8 + (qc & 1);
            const float vv[4] = {bv[j].x, bv[j].y, bv[j].z, bv[j].w};
#pragma unroll
            for (int e = 0; e < 4; e++) {
                if (PASSES == 3) {
                    uint32_t hi, lo;
                    tf32_split(vv[e], hi, lo);
                    dh[e * 2] = hi;
                    dl[e * 2] = lo;
                } else {
                    dh[e * 2] = tf32_of(vv[e]);
                }
            }
        }
    };

    float acc[2][8][4];
#pragma unroll
    for (int mt = 0; mt < 2; mt++)
#pragma unroll
        for (int nt = 0; nt < 8; nt++)
#pragma unroll
            for (int e = 0; e < 4; e++) acc[mt][nt][e] = 0.0f;

    const int nk = K / BK;

    // prologue
    ldg(0);
    store_stage(0);
    __syncthreads();

    for (int i = 0; i < nk; i++) {
        const int cur = i & 1;
        const bool more = (i + 1) < nk;
        if (more) ldg((i + 1) * BK);

        const uint32_t* sbase = sm + cur * STG_U32;
#pragma unroll
        for (int ks = 0; ks < 2; ks++) {
            uint32_t aHi[2][4], aLo[2][4];
#pragma unroll
            for (int mt = 0; mt < 2; mt++) {
                const int ablk = ((warpM * 2 + mt) * 2 + ks) * A_BLK + lane * 4;
                *(uint4*)aHi[mt] = *(const uint4*)(sbase + OFF_AHI + ablk);
                if (PASSES == 3)
                    *(uint4*)aLo[mt] = *(const uint4*)(sbase + OFF_ALO + ablk);
            }
#pragma unroll
            for (int h = 0; h < 2; h++) {
                uint32_t bHi[4][2], bLo[4][2];
#pragma unroll
                for (int n4 = 0; n4 < 4; n4++) {
                    const int bblk = ((warpN * 8 + h * 4 + n4) * 2 + ks) * B_BLK + lane * 2;
                    *(uint2*)bHi[n4] = *(const uint2*)(sbase + OFF_BHI + bblk);
                    if (PASSES == 3)
                        *(uint2*)bLo[n4] = *(const uint2*)(sbase + OFF_BLO + bblk);
                }
#pragma unroll
                for (int mt = 0; mt < 2; mt++)
#pragma unroll
                    for (int n4 = 0; n4 < 4; n4++) {
                        float* c = acc[mt][h * 4 + n4];
                        mma_tf32(c, aHi[mt], bHi[n4]);
                        if (PASSES == 3) {
                            mma_tf32(c, aHi[mt], bLo[n4]);
                            mma_tf32(c, aLo[mt], bHi[n4]);
                        }
                    }
            }
        }

        if (more) store_stage(cur ^ 1);
        __syncthreads();
    }

    // epilogue
    const int gID = lane >> 2, tig = lane & 3;
#pragma unroll
    for (int mt = 0; mt < 2; mt++) {
        const int r0 = rowBase + warpM * 32 + mt * 16 + gID;
#pragma unroll
        for (int nt = 0; nt < 8; nt++) {
            const int col = colBase + warpN * 64 + nt * 8 + tig * 2;
            float b0 = bias ? bias[col] : 0.f;
            float b1 = bias ? bias[col + 1] : 0.f;
            float2 o0 = {acc[mt][nt][0] * scale + b0, acc[mt][nt][1] * scale + b1};
            float2 o1 = {acc[mt][nt][2] * scale + b0, acc[mt][nt][3] * scale + b1};
            *(float2*)(C + (size_t)r0 * ldc + col) = o0;
            *(float2*)(C + (size_t)(r0 + 8) * ldc + col) = o1;
        }
    }
}

// ------------------------- transpose (K-major prep) ------------------------
__global__ void transpose_k(const float* __restrict__ in, float* __restrict__ out,
                            int R, int C, long long sIn, long long sOut) {
    __shared__ float t[32][33];
    in  += (long long)blockIdx.z * sIn;
    out += (long long)blockIdx.z * sOut;
    const int c0 = blockIdx.x * 32, r0 = blockIdx.y * 32;
#pragma unroll
    for (int i = 0; i < 4; i++)
        t[threadIdx.y + i * 8][threadIdx.x] =
            in[(size_t)(r0 + threadIdx.y + i * 8) * C + c0 + threadIdx.x];
    __syncthreads();
#pragma unroll
    for (int i = 0; i < 4; i++)
        out[(size_t)(c0 + threadIdx.y + i * 8) * R + r0 + threadIdx.x] =
            t[threadIdx.x][threadIdx.y + i * 8];
}

// ------------------------------- softmax -----------------------------------
__global__ void softmax_rows(float* __restrict__ S, int ncols) {
    float* row = S + (size_t)blockIdx.x * ncols;
    const int tid = threadIdx.x;
    __shared__ float red[8];

    float m = -3.402823466e38f;
    for (int c = tid; c < ncols; c += 256) m = fmaxf(m, row[c]);
#pragma unroll
    for (int o = 16; o > 0; o >>= 1) m = fmaxf(m, __shfl_xor_sync(0xffffffffu, m, o));
    if ((tid & 31) == 0) red[tid >> 5] = m;
    __syncthreads();
    m = red[0];
#pragma unroll
    for (int i = 1; i < 8; i++) m = fmaxf(m, red[i]);

    float s = 0.0f;
    for (int c = tid; c < ncols; c += 256) {
        float e = expf(row[c] - m);
        row[c] = e;
        s += e;
    }
#pragma unroll
    for (int o = 16; o > 0; o >>= 1) s += __shfl_xor_sync(0xffffffffu, s, o);
    __syncthreads();
    if ((tid & 31) == 0) red[tid >> 5] = s;
    __syncthreads();
    s = 0.0f;
#pragma unroll
    for (int i = 0; i < 8; i++) s += red[i];
    const float inv = 1.0f / s;
    for (int c = tid; c < ncols; c += 256) row[c] *= inv;
}

// ------------------------------- launcher ----------------------------------
extern "C" void kernel_launch(void* const* d_in, const int* in_sizes, int n_in,
                              void* d_out, int out_size) {
    const float* q  = (const float*)d_in[0];
    const float* k  = (const float*)d_in[1];
    const float* v  = (const float*)d_in[2];
    const float* Wq = (const float*)d_in[3];
    const float* Wk = (const float*)d_in[4];
    const float* Wv = (const float*)d_in[5];
    const float* bq = (const float*)d_in[6];
    const float* bk = (const float*)d_in[7];
    const float* bv = (const float*)d_in[8];
    float* out = (float*)d_out;

    float *Qp, *Kp, *Vp, *Vtp, *Sp, *Wtp;
    cudaGetSymbolAddress((void**)&Qp,  g_Q);
    cudaGetSymbolAddress((void**)&Kp,  g_K);
    cudaGetSymbolAddress((void**)&Vp,  g_V);
    cudaGetSymbolAddress((void**)&Vtp, g_Vt);
    cudaGetSymbolAddress((void**)&Sp,  g_S);
    cudaGetSymbolAddress((void**)&Wtp, g_Wt);

    static int smem_set = 0;
    if (!smem_set) {
        cudaFuncSetAttribute(gemm_tf32<3>, cudaFuncAttributeMaxDynamicSharedMemorySize, SMEM_BYTES);
        cudaFuncSetAttribute(gemm_tf32<1>, cudaFuncAttributeMaxDynamicSharedMemorySize, SMEM_BYTES);
        smem_set = 1;
    }

    const dim3 tthr(32, 8);

    // 1) projections: C = X @ W + b  (Wt = W^T, K-major)
    dim3 gproj(MODEL / BN, MTOT / BM, 1);           // (8, 64)
    transpose_k<<<dim3(32, 32, 1), tthr>>>(Wq, Wtp, MODEL, MODEL, 0, 0);
    gemm_tf32<3><<<gproj, NTHREADS, SMEM_BYTES>>>(q, MODEL, Wtp, MODEL, Qp, MODEL, bq, 1.0f, MODEL, 0, 0, 0);
    transpose_k<<<dim3(32, 32, 1), tthr>>>(Wk, Wtp, MODEL, MODEL, 0, 0);
    gemm_tf32<3><<<gproj, NTHREADS, SMEM_BYTES>>>(k, MODEL, Wtp, MODEL, Kp, MODEL, bk, 1.0f, MODEL, 0, 0, 0);
    transpose_k<<<dim3(32, 32, 1), tthr>>>(Wv, Wtp, MODEL, MODEL, 0, 0);
    gemm_tf32<1><<<gproj, NTHREADS, SMEM_BYTES>>>(v, MODEL, Wtp, MODEL, Vp, MODEL, bv, 1.0f, MODEL, 0, 0, 0);

    // 2) scores: S[b] = (Q[b] @ K[b]^T) / 32
    dim3 gsc(SEQ / BN, SEQ / BM, BATCH);            // (16, 16, 4)
    gemm_tf32<3><<<gsc, NTHREADS, SMEM_BYTES>>>(Qp, MODEL, Kp, MODEL, Sp, SEQ, nullptr, 0.03125f,
                                                MODEL, (long long)SEQ * MODEL, (long long)SEQ * MODEL,
                                                (long long)SEQ * SEQ);

    // 3) softmax rows
    softmax_rows<<<BATCH * SEQ, 256>>>(Sp, SEQ);

    // 4) Vt[b] = V[b]^T
    transpose_k<<<dim3(MODEL / 32, SEQ / 32, BATCH), tthr>>>(Vp, Vtp, SEQ, MODEL,
                                                             (long long)SEQ * MODEL,
                                                             (long long)SEQ * MODEL);

    // 5) O[b] = P[b] @ Vt[b]^T  (single-pass tf32)
    dim3 gpv(MODEL / BN, SEQ / BM, BATCH);          // (8, 16, 4)
    gemm_tf32<1><<<gpv, NTHREADS, SMEM_BYTES>>>(Sp, SEQ, Vtp, SEQ, out, MODEL, nullptr, 1.0f,
                                                SEQ, (long long)SEQ * SEQ, (long long)SEQ * MODEL,
                                                (long long)SEQ * MODEL);
}

// round 5
// speedup vs baseline: 2.5600x; 1.4424x over previous
#include <cuda_runtime.h>
#include <cuda_fp16.h>
#include <cstdint>
#include <math.h>

// ---------------------------------------------------------------------------
// DotProductAttention (sm_103 plain target -> mma.sync).
// fp16 m16n8k16 3-term hi/lo split (== tf32-3x precision, 2x rate) for
// Q proj, K proj, scores (exp-amplified stages).
// tf32 m16n8k8 single-pass for V proj and PV (linear stages).
// ---------------------------------------------------------------------------

#define BATCH 4
#define SEQ   2048
#define MODEL 1024
#define MTOT  (BATCH * SEQ)   // 8192

__device__ float g_Q [MTOT * MODEL];
__device__ float g_K [MTOT * MODEL];
__device__ float g_V [MTOT * MODEL];
__device__ float g_Vt[MTOT * MODEL];
__device__ float g_S [(size_t)BATCH * SEQ * SEQ];
__device__ float g_Wt[MODEL * MODEL];

#define BM 128
#define BN 128
#define NTHREADS 256

// ========================= fp16 3x kernel (BK=16) ==========================
#define F16_A_TILE 132                    // words per 16x16 A tile (512B + pad)
#define F16_B_TILE 68                     // words per 8x16 B tile (256B + pad)
#define OFF_FAHI 0
#define OFF_FALO (8 * F16_A_TILE)         // 1056
#define OFF_FBHI (2 * 8 * F16_A_TILE)     // 2112
#define OFF_FBLO (OFF_FBHI + 16 * F16_B_TILE)  // 3200
#define F16_STG  (OFF_FBLO + 16 * F16_B_TILE)  // 4288 words
#define F16_SMEM_BYTES (2 * F16_STG * 4)  // 34304

__device__ __forceinline__ void f16_split2(float a, float b, uint32_t& hi, uint32_t& lo) {
    __half ha = __float2half_rn(a), hb = __float2half_rn(b);
    __half la = __float2half_rn(a - __half2float(ha));
    __half lb = __float2half_rn(b - __half2float(hb));
    hi = ((uint32_t)__half_as_ushort(hb) << 16) | (uint32_t)__half_as_ushort(ha);
    lo = ((uint32_t)__half_as_ushort(lb) << 16) | (uint32_t)__half_as_ushort(la);
}

__device__ __forceinline__ void mma_f16(float* c, const uint32_t* a, const uint32_t* b) {
    asm volatile(
        "mma.sync.aligned.m16n8k16.row.col.f32.f16.f16.f32 "
        "{%0,%1,%2,%3}, {%4,%5,%6,%7}, {%8,%9}, {%0,%1,%2,%3};"
        : "+f"(c[0]), "+f"(c[1]), "+f"(c[2]), "+f"(c[3])
        : "r"(a[0]), "r"(a[1]), "r"(a[2]), "r"(a[3]), "r"(b[0]), "r"(b[1]));
}

// C[M,N] = scale * (A[M,K] @ B[N,K]^T) + bias; A,B K-major fp32; batched z.
__global__ void __launch_bounds__(NTHREADS, 2) gemm_f16_3x(
    const float* __restrict__ A, int lda,
    const float* __restrict__ B, int ldb,
    float* __restrict__ C, int ldc,
    const float* __restrict__ bias, float scale, int K,
    long long sA, long long sB, long long sC)
{
    extern __shared__ uint32_t sm[];
    const int tid = threadIdx.x;
    const int wid = tid >> 5, lane = tid & 31;
    const int warpM = wid & 3;    // 4 bands of 32 rows (2 m-tiles)
    const int warpN = wid >> 2;   // 2 bands of 64 cols (8 n-tiles)

    A += (long long)blockIdx.z * sA;
    B += (long long)blockIdx.z * sB;
    C += (long long)blockIdx.z * sC;
    const int rowBase = blockIdx.y * BM;
    const int colBase = blockIdx.x * BN;

    // staging: thread covers rows r0 and r0+64 at k-quad qc (BK=16 -> qc 0..3)
    const int r0 = tid >> 2, qc = tid & 3;
    const int lane0 = ((r0 & 7) << 2) + ((qc & 1) << 1);
    const int p0 = lane0 ^ ((lane0 >> 3) & 1);
    const int p1 = (lane0 + 1) ^ (((lane0 + 1) >> 3) & 1);
    const int regA = ((r0 >> 3) & 1) | (qc & 2);      // same for r0+64
    const int regB = (qc >> 1) & 1;

    float4 pA0, pA1, pB0, pB1;

    auto ldg = [&](int kt) {
        pA0 = *(const float4*)(A + (size_t)(rowBase + r0) * lda + kt + qc * 4);
        pA1 = *(const float4*)(A + (size_t)(rowBase + r0 + 64) * lda + kt + qc * 4);
        pB0 = *(const float4*)(B + (size_t)(colBase + r0) * ldb + kt + qc * 4);
        pB1 = *(const float4*)(B + (size_t)(colBase + r0 + 64) * ldb + kt + qc * 4);
    };

    auto store_stage = [&](int stg) {
        uint32_t* base = sm + stg * F16_STG;
        const float4 av[2] = {pA0, pA1};
        const float4 bv[2] = {pB0, pB1};
#pragma unroll
        for (int j = 0; j < 2; j++) {
            const int r = r0 + j * 64;
            // ---- A tile (mt = r>>4) ----
            {
                uint32_t* th = base + OFF_FAHI + (r >> 4) * F16_A_TILE;
                uint32_t* tl = base + OFF_FALO + (r >> 4) * F16_A_TILE;
                uint32_t h0, l0, h1, l1;
                f16_split2(av[j].x, av[j].y, h0, l0);
                f16_split2(av[j].z, av[j].w, h1, l1);
                th[p0 * 4 + regA] = h0;
                th[p1 * 4 + regA] = h1;
                tl[p0 * 4 + regA] = l0;
                tl[p1 * 4 + regA] = l1;
            }
            // ---- B tile (nt = r>>3) ----
            {
                uint32_t* th = base + OFF_FBHI + (r >> 3) * F16_B_TILE;
                uint32_t* tl = base + OFF_FBLO + (r >> 3) * F16_B_TILE;
                uint32_t h0, l0, h1, l1;
                f16_split2(bv[j].x, bv[j].y, h0, l0);
                f16_split2(bv[j].z, bv[j].w, h1, l1);
                th[lane0 * 2 + regB] = h0;
                th[(lane0 + 1) * 2 + regB] = h1;
                tl[lane0 * 2 + regB] = l0;
                tl[(lane0 + 1) * 2 + regB] = l1;
            }
        }
    };

    float acc[2][8][4];
#pragma unroll
    for (int mt = 0; mt < 2; mt++)
#pragma unroll
        for (int nt = 0; nt < 8; nt++)
#pragma unroll
            for (int e = 0; e < 4; e++) acc[mt][nt][e] = 0.0f;

    const int physLane = lane ^ ((lane >> 3) & 1);
    const int nk = K / 16;

    ldg(0);
    store_stage(0);
    __syncthreads();

    for (int i = 0; i < nk; i++) {
        const int cur = i & 1;
        const bool more = (i + 1) < nk;
        if (more) ldg((i + 1) * 16);

        const uint32_t* sb = sm + cur * F16_STG;
        uint32_t aHi[2][4], aLo[2][4];
#pragma unroll
        for (int mt = 0; mt < 2; mt++) {
            const uint32_t* ap = sb + OFF_FAHI + (warpM * 2 + mt) * F16_A_TILE + physLane * 4;
            *(uint4*)aHi[mt] = *(const uint4*)ap;
            *(uint4*)aLo[mt] = *(const uint4*)(ap + (OFF_FALO - OFF_FAHI));
        }
#pragma unroll
        for (int h = 0; h < 2; h++) {
            uint32_t bHi[4][2], bLo[4][2];
#pragma unroll
            for (int n4 = 0; n4 < 4; n4++) {
                const uint32_t* bp = sb + OFF_FBHI + (warpN * 8 + h * 4 + n4) * F16_B_TILE + lane * 2;
                *(uint2*)bHi[n4] = *(const uint2*)bp;
                *(uint2*)bLo[n4] = *(const uint2*)(bp + (OFF_FBLO - OFF_FBHI));
            }
#pragma unroll
            for (int mt = 0; mt < 2; mt++)
#pragma unroll
                for (int n4 = 0; n4 < 4; n4++) {
                    float* c = acc[mt][h * 4 + n4];
                    mma_f16(c, aHi[mt], bHi[n4]);
                    mma_f16(c, aHi[mt], bLo[n4]);
                    mma_f16(c, aLo[mt], bHi[n4]);
                }
        }

        if (more) store_stage(cur ^ 1);
        __syncthreads();
    }

    // epilogue (same C fragment layout as m16n8k8)
    const int gID = lane >> 2, tig = lane & 3;
#pragma unroll
    for (int mt = 0; mt < 2; mt++) {
        const int rr = rowBase + warpM * 32 + mt * 16 + gID;
#pragma unroll
        for (int nt = 0; nt < 8; nt++) {
            const int col = colBase + warpN * 64 + nt * 8 + tig * 2;
            float b0 = bias ? bias[col] : 0.f;
            float b1 = bias ? bias[col + 1] : 0.f;
            float2 o0 = {acc[mt][nt][0] * scale + b0, acc[mt][nt][1] * scale + b1};
            float2 o1 = {acc[mt][nt][2] * scale + b0, acc[mt][nt][3] * scale + b1};
            *(float2*)(C + (size_t)rr * ldc + col) = o0;
            *(float2*)(C + (size_t)(rr + 8) * ldc + col) = o1;
        }
    }
}

// ===================== tf32 single-pass kernel (BK=16) =====================
#define A_BLK 132
#define B_BLK 66
#define OFF_AHI 0
#define OFF_BHI 2112       // 16 blocks * 132
#define STG_U32 4224       // + 32 blocks * 66 = 2112
#define SMEM_TF32_BYTES (2 * STG_U32 * 4)   // 33792

__device__ __forceinline__ uint32_t tf32_of(float v) {
    uint32_t r;
    asm("cvt.rna.tf32.f32 %0, %1;" : "=r"(r) : "f"(v));
    return r;
}
__device__ __forceinline__ void mma_tf32(float* c, const uint32_t* a, const uint32_t* b) {
    asm volatile(
        "mma.sync.aligned.m16n8k8.row.col.f32.tf32.tf32.f32 "
        "{%0,%1,%2,%3}, {%4,%5,%6,%7}, {%8,%9}, {%0,%1,%2,%3};"
        : "+f"(c[0]), "+f"(c[1]), "+f"(c[2]), "+f"(c[3])
        : "r"(a[0]), "r"(a[1]), "r"(a[2]), "r"(a[3]), "r"(b[0]), "r"(b[1]));
}

__global__ void __launch_bounds__(NTHREADS, 2) gemm_tf32_1(
    const float* __restrict__ A, int lda,
    const float* __restrict__ B, int ldb,
    float* __restrict__ C, int ldc,
    const float* __restrict__ bias, float scale, int K,
    long long sA, long long sB, long long sC)
{
    extern __shared__ uint32_t sm[];
    const int tid = threadIdx.x;
    const int wid = tid >> 5, lane = tid & 31;
    const int warpM = wid & 3;
    const int warpN = wid >> 2;

    A += (long long)blockIdx.z * sA;
    B += (long long)blockIdx.z * sB;
    C += (long long)blockIdx.z * sC;
    const int rowBase = blockIdx.y * BM;
    const int colBase = blockIdx.x * BN;

    const int f40 = tid, f41 = 256 + tid;
    const int rA0 = f40 >> 2, cA0 = f40 & 3;
    const int rA1 = f41 >> 2, cA1 = f41 & 3;

    float4 pfA0, pfA1, pfB0, pfB1;

    auto ldg = [&](int kt) {
        pfA0 = *(const float4*)(A + (size_t)(rowBase + rA0) * lda + kt + cA0 * 4);
        pfA1 = *(const float4*)(A + (size_t)(rowBase + rA1) * lda + kt + cA1 * 4);
        pfB0 = *(const float4*)(B + (size_t)(colBase + rA0) * ldb + kt + cA0 * 4);
        pfB1 = *(const float4*)(B + (size_t)(colBase + rA1) * ldb + kt + cA1 * 4);
    };

    auto store_stage = [&](int stg) {
        uint32_t* base = sm + stg * STG_U32;
        const float4 av[2] = {pfA0, pfA1};
        const int rAs[2] = {rA0, rA1}, cAs[2] = {cA0, cA1};
#pragma unroll
        for (int j = 0; j < 2; j++) {
            const int r = rAs[j], qc = cAs[j];
            const int mt = r >> 4, rr = r & 15, ks = qc >> 1;
            const int reg = (rr >> 3) + ((qc & 1) << 1);
            uint32_t* dh = base + OFF_AHI + (mt * 2 + ks) * A_BLK + (rr & 7) * 16 + reg;
            const float vv[4] = {av[j].x, av[j].y, av[j].z, av[j].w};
#pragma unroll
            for (int e = 0; e < 4; e++) dh[e * 4] = tf32_of(vv[e]);
        }
        const float4 bv[2] = {pfB0, pfB1};
#pragma unroll
        for (int j = 0; j < 2; j++) {
            const int rn = rAs[j], qc = cAs[j];
            const int nt = rn >> 3, nn = rn & 7, ks = qc >> 1;
            uint32_t* dh = base + OFF_BHI + (nt * 2 + ks) * B_BLK + nn * 8 + (qc & 1);
            const float vv[4] = {bv[j].x, bv[j].y, bv[j].z, bv[j].w};
#pragma unroll
            for (int e = 0; e < 4; e++) dh[e * 2] = tf32_of(vv[e]);
        }
    };

    float acc[2][8][4];
#pragma unroll
    for (int mt = 0; mt < 2; mt++)
#pragma unroll
        for (int nt = 0; nt < 8; nt++)
#pragma unroll
            for (int e = 0; e < 4; e++) acc[mt][nt][e] = 0.0f;

    const int nk = K / 16;

    ldg(0);
    store_stage(0);
    __syncthreads();

    for (int i = 0; i < nk; i++) {
        const int cur = i & 1;
        const bool more = (i + 1) < nk;
        if (more) ldg((i + 1) * 16);

        const uint32_t* sbase = sm + cur * STG_U32;
#pragma unroll
        for (int ks = 0; ks < 2; ks++) {
            uint32_t aHi[2][4];
#pragma unroll
            for (int mt = 0; mt < 2; mt++) {
                const int ablk = ((warpM * 2 + mt) * 2 + ks) * A_BLK + lane * 4;
                *(uint4*)aHi[mt] = *(const uint4*)(sbase + OFF_AHI + ablk);
            }
#pragma unroll
            for (int h = 0; h < 2; h++) {
                uint32_t bHi[4][2];
#pragma unroll
                for (int n4 = 0; n4 < 4; n4++) {
                    const int bblk = ((warpN * 8 + h * 4 + n4) * 2 + ks) * B_BLK + lane * 2;
                    *(uint2*)bHi[n4] = *(const uint2*)(sbase + OFF_BHI + bblk);
                }
#pragma unroll
                for (int mt = 0; mt < 2; mt++)
#pragma unroll
                    for (int n4 = 0; n4 < 4; n4++)
                        mma_tf32(acc[mt][h * 4 + n4], aHi[mt], bHi[n4]);
            }
        }

        if (more) store_stage(cur ^ 1);
        __syncthreads();
    }

    const int gID = lane >> 2, tig = lane & 3;
#pragma unroll
    for (int mt = 0; mt < 2; mt++) {
        const int r0 = rowBase + warpM * 32 + mt * 16 + gID;
#pragma unroll
        for (int nt = 0; nt < 8; nt++) {
            const int col = colBase + warpN * 64 + nt * 8 + tig * 2;
            float b0 = bias ? bias[col] : 0.f;
            float b1 = bias ? bias[col + 1] : 0.f;
            float2 o0 = {acc[mt][nt][0] * scale + b0, acc[mt][nt][1] * scale + b1};
            float2 o1 = {acc[mt][nt][2] * scale + b0, acc[mt][nt][3] * scale + b1};
            *(float2*)(C + (size_t)r0 * ldc + col) = o0;
            *(float2*)(C + (size_t)(r0 + 8) * ldc + col) = o1;
        }
    }
}

// ------------------------- transpose (K-major prep) ------------------------
__global__ void transpose_k(const float* __restrict__ in, float* __restrict__ out,
                            int R, int C, long long sIn, long long sOut) {
    __shared__ float t[32][33];
    in  += (long long)blockIdx.z * sIn;
    out += (long long)blockIdx.z * sOut;
    const int c0 = blockIdx.x * 32, r0 = blockIdx.y * 32;
#pragma unroll
    for (int i = 0; i < 4; i++)
        t[threadIdx.y + i * 8][threadIdx.x] =
            in[(size_t)(r0 + threadIdx.y + i * 8) * C + c0 + threadIdx.x];
    __syncthreads();
#pragma unroll
    for (int i = 0; i < 4; i++)
        out[(size_t)(c0 + threadIdx.y + i * 8) * R + r0 + threadIdx.x] =
            t[threadIdx.x][threadIdx.y + i * 8];
}

// ------------------------------- softmax -----------------------------------
__global__ void softmax_rows(float* __restrict__ S, int ncols) {
    float* row = S + (size_t)blockIdx.x * ncols;
    const int tid = threadIdx.x;
    __shared__ float red[8];

    float m = -3.402823466e38f;
    for (int c = tid; c < ncols; c += 256) m = fmaxf(m, row[c]);
#pragma unroll
    for (int o = 16; o > 0; o >>= 1) m = fmaxf(m, __shfl_xor_sync(0xffffffffu, m, o));
    if ((tid & 31) == 0) red[tid >> 5] = m;
    __syncthreads();
    m = red[0];
#pragma unroll
    for (int i = 1; i < 8; i++) m = fmaxf(m, red[i]);

    float s = 0.0f;
    for (int c = tid; c < ncols; c += 256) {
        float e = expf(row[c] - m);
        row[c] = e;
        s += e;
    }
#pragma unroll
    for (int o = 16; o > 0; o >>= 1) s += __shfl_xor_sync(0xffffffffu, s, o);
    __syncthreads();
    if ((tid & 31) == 0) red[tid >> 5] = s;
    __syncthreads();
    s = 0.0f;
#pragma unroll
    for (int i = 0; i < 8; i++) s += red[i];
    const float inv = 1.0f / s;
    for (int c = tid; c < ncols; c += 256) row[c] *= inv;
}

// ------------------------------- launcher ----------------------------------
extern "C" void kernel_launch(void* const* d_in, const int* in_sizes, int n_in,
                              void* d_out, int out_size) {
    const float* q  = (const float*)d_in[0];
    const float* k  = (const float*)d_in[1];
    const float* v  = (const float*)d_in[2];
    const float* Wq = (const float*)d_in[3];
    const float* Wk = (const float*)d_in[4];
    const float* Wv = (const float*)d_in[5];
    const float* bq = (const float*)d_in[6];
    const float* bk = (const float*)d_in[7];
    const float* bv = (const float*)d_in[8];
    float* out = (float*)d_out;

    float *Qp, *Kp, *Vp, *Vtp, *Sp, *Wtp;
    cudaGetSymbolAddress((void**)&Qp,  g_Q);
    cudaGetSymbolAddress((void**)&Kp,  g_K);
    cudaGetSymbolAddress((void**)&Vp,  g_V);
    cudaGetSymbolAddress((void**)&Vtp, g_Vt);
    cudaGetSymbolAddress((void**)&Sp,  g_S);
    cudaGetSymbolAddress((void**)&Wtp, g_Wt);

    static int smem_set = 0;
    if (!smem_set) {
        cudaFuncSetAttribute(gemm_f16_3x, cudaFuncAttributeMaxDynamicSharedMemorySize, F16_SMEM_BYTES);
        cudaFuncSetAttribute(gemm_tf32_1, cudaFuncAttributeMaxDynamicSharedMemorySize, SMEM_TF32_BYTES);
        smem_set = 1;
    }

    const dim3 tthr(32, 8);

    // 1) projections (Wt = W^T, K-major)
    dim3 gproj(MODEL / BN, MTOT / BM, 1);           // (8, 64)
    transpose_k<<<dim3(32, 32, 1), tthr>>>(Wq, Wtp, MODEL, MODEL, 0, 0);
    gemm_f16_3x<<<gproj, NTHREADS, F16_SMEM_BYTES>>>(q, MODEL, Wtp, MODEL, Qp, MODEL, bq, 1.0f, MODEL, 0, 0, 0);
    transpose_k<<<dim3(32, 32, 1), tthr>>>(Wk, Wtp, MODEL, MODEL, 0, 0);
    gemm_f16_3x<<<gproj, NTHREADS, F16_SMEM_BYTES>>>(k, MODEL, Wtp, MODEL, Kp, MODEL, bk, 1.0f, MODEL, 0, 0, 0);
    transpose_k<<<dim3(32, 32, 1), tthr>>>(Wv, Wtp, MODEL, MODEL, 0, 0);
    gemm_tf32_1<<<gproj, NTHREADS, SMEM_TF32_BYTES>>>(v, MODEL, Wtp, MODEL, Vp, MODEL, bv, 1.0f, MODEL, 0, 0, 0);

    // 2) scores: S[b] = (Q[b] @ K[b]^T) / 32
    dim3 gsc(SEQ / BN, SEQ / BM, BATCH);            // (16, 16, 4)
    gemm_f16_3x<<<gsc, NTHREADS, F16_SMEM_BYTES>>>(Qp, MODEL, Kp, MODEL, Sp, SEQ, nullptr, 0.03125f,
                                                   MODEL, (long long)SEQ * MODEL, (long long)SEQ * MODEL,
                                                   (long long)SEQ * SEQ);

    // 3) softmax rows
    softmax_rows<<<BATCH * SEQ, 256>>>(Sp, SEQ);

    // 4) Vt[b] = V[b]^T
    transpose_k<<<dim3(MODEL / 32, SEQ / 32, BATCH), tthr>>>(Vp, Vtp, SEQ, MODEL,
                                                             (long long)SEQ * MODEL,
                                                             (long long)SEQ * MODEL);

    // 5) O[b] = P[b] @ Vt[b]^T  (single-pass tf32)
    dim3 gpv(MODEL / BN, SEQ / BM, BATCH);          // (8, 16, 4)
    gemm_tf32_1<<<gpv, NTHREADS, SMEM_TF32_BYTES>>>(Sp, SEQ, Vtp, SEQ, out, MODEL, nullptr, 1.0f,
                                                    SEQ, (long long)SEQ * SEQ, (long long)SEQ * MODEL,
                                                    (long long)SEQ * MODEL);
}

// round 6
// speedup vs baseline: 2.9162x; 1.1391x over previous
#include <cuda_runtime.h>
#include <cuda_fp16.h>
#include <cstdint>
#include <math.h>

// ---------------------------------------------------------------------------
// DotProductAttention (sm_103 plain target -> mma.sync m16n8k16 fp16).
// 3-term hi/lo fp16 split (== fp32-grade) for Q proj, K proj, scores.
// Single-pass fp16 (== tf32 precision, 2x rate) for V proj and PV.
// ---------------------------------------------------------------------------

#define BATCH 4
#define SEQ   2048
#define MODEL 1024
#define MTOT  (BATCH * SEQ)   // 8192

__device__ float g_Q [MTOT * MODEL];
__device__ float g_K [MTOT * MODEL];
__device__ float g_V [MTOT * MODEL];
__device__ float g_Vt[MTOT * MODEL];
__device__ float g_S [(size_t)BATCH * SEQ * SEQ];
__device__ float g_Wt[MODEL * MODEL];

#define BM 128
#define BN 128
#define NTHREADS 256

#define F16_A_TILE 132                    // words per 16x16 A tile (512B + pad)
#define F16_B_TILE 68                     // words per 8x16 B tile (256B + pad)

__device__ __forceinline__ void f16_split2(float a, float b, uint32_t& hi, uint32_t& lo) {
    __half ha = __float2half_rn(a), hb = __float2half_rn(b);
    __half la = __float2half_rn(a - __half2float(ha));
    __half lb = __float2half_rn(b - __half2float(hb));
    hi = ((uint32_t)__half_as_ushort(hb) << 16) | (uint32_t)__half_as_ushort(ha);
    lo = ((uint32_t)__half_as_ushort(lb) << 16) | (uint32_t)__half_as_ushort(la);
}
__device__ __forceinline__ uint32_t f16_pack2(float a, float b) {
    __half ha = __float2half_rn(a), hb = __float2half_rn(b);
    return ((uint32_t)__half_as_ushort(hb) << 16) | (uint32_t)__half_as_ushort(ha);
}
__device__ __forceinline__ void mma_f16(float* c, const uint32_t* a, const uint32_t* b) {
    asm volatile(
        "mma.sync.aligned.m16n8k16.row.col.f32.f16.f16.f32 "
        "{%0,%1,%2,%3}, {%4,%5,%6,%7}, {%8,%9}, {%0,%1,%2,%3};"
        : "+f"(c[0]), "+f"(c[1]), "+f"(c[2]), "+f"(c[3])
        : "r"(a[0]), "r"(a[1]), "r"(a[2]), "r"(a[3]), "r"(b[0]), "r"(b[1]));
}

// C[M,N] = scale * (A[M,K] @ B[N,K]^T) + bias; A,B K-major fp32; batched z.
template <int PASSES>
__global__ void __launch_bounds__(NTHREADS, 2) gemm_f16(
    const float* __restrict__ A, int lda,
    const float* __restrict__ B, int ldb,
    float* __restrict__ C, int ldc,
    const float* __restrict__ bias, float scale, int K,
    long long sA, long long sB, long long sC)
{
    constexpr bool P3 = (PASSES == 3);
    constexpr int NA = P3 ? 2 : 1;
    constexpr int OFF_ALO = 8 * F16_A_TILE;               // valid iff P3
    constexpr int OFF_BHI = NA * 8 * F16_A_TILE;
    constexpr int OFF_BLO = OFF_BHI + 16 * F16_B_TILE;    // valid iff P3
    constexpr int STG = OFF_BHI + NA * 16 * F16_B_TILE;

    extern __shared__ uint32_t sm[];
    const int tid = threadIdx.x;
    const int wid = tid >> 5, lane = tid & 31;
    const int warpM = wid & 3;    // 4 bands of 32 rows (2 m-tiles)
    const int warpN = wid >> 2;   // 2 bands of 64 cols (8 n-tiles)

    A += (long long)blockIdx.z * sA;
    B += (long long)blockIdx.z * sB;
    C += (long long)blockIdx.z * sC;
    const int rowBase = blockIdx.y * BM;
    const int colBase = blockIdx.x * BN;

    // staging: thread covers rows r0 and r0+64 at k-quad qc (BK=16 -> qc 0..3)
    const int r0 = tid >> 2, qc = tid & 3;
    const int lane0 = ((r0 & 7) << 2) + ((qc & 1) << 1);
    const int p0 = lane0 ^ ((lane0 >> 3) & 1);
    const int p1 = (lane0 + 1) ^ (((lane0 + 1) >> 3) & 1);
    const int regA = ((r0 >> 3) & 1) | (qc & 2);
    const int regB = (qc >> 1) & 1;

    float4 pA0, pA1, pB0, pB1;

    auto ldg = [&](int kt) {
        pA0 = *(const float4*)(A + (size_t)(rowBase + r0) * lda + kt + qc * 4);
        pA1 = *(const float4*)(A + (size_t)(rowBase + r0 + 64) * lda + kt + qc * 4);
        pB0 = *(const float4*)(B + (size_t)(colBase + r0) * ldb + kt + qc * 4);
        pB1 = *(const float4*)(B + (size_t)(colBase + r0 + 64) * ldb + kt + qc * 4);
    };

    auto store_stage = [&](int stg) {
        uint32_t* base = sm + stg * STG;
        const float4 av[2] = {pA0, pA1};
        const float4 bv[2] = {pB0, pB1};
#pragma unroll
        for (int j = 0; j < 2; j++) {
            const int r = r0 + j * 64;
            {   // ---- A tile (mt = r>>4) ----
                uint32_t* th = base + (r >> 4) * F16_A_TILE;
                if (P3) {
                    uint32_t* tl = th + OFF_ALO;
                    uint32_t h0, l0, h1, l1;
                    f16_split2(av[j].x, av[j].y, h0, l0);
                    f16_split2(av[j].z, av[j].w, h1, l1);
                    th[p0 * 4 + regA] = h0;
                    th[p1 * 4 + regA] = h1;
                    tl[p0 * 4 + regA] = l0;
                    tl[p1 * 4 + regA] = l1;
                } else {
                    th[p0 * 4 + regA] = f16_pack2(av[j].x, av[j].y);
                    th[p1 * 4 + regA] = f16_pack2(av[j].z, av[j].w);
                }
            }
            {   // ---- B tile (nt = r>>3) ----
                uint32_t* th = base + OFF_BHI + (r >> 3) * F16_B_TILE;
                if (P3) {
                    uint32_t* tl = th + (OFF_BLO - OFF_BHI);
                    uint32_t h0, l0, h1, l1;
                    f16_split2(bv[j].x, bv[j].y, h0, l0);
                    f16_split2(bv[j].z, bv[j].w, h1, l1);
                    th[lane0 * 2 + regB] = h0;
                    th[(lane0 + 1) * 2 + regB] = h1;
                    tl[lane0 * 2 + regB] = l0;
                    tl[(lane0 + 1) * 2 + regB] = l1;
                } else {
                    th[lane0 * 2 + regB] = f16_pack2(bv[j].x, bv[j].y);
                    th[(lane0 + 1) * 2 + regB] = f16_pack2(bv[j].z, bv[j].w);
                }
            }
        }
    };

    float acc[2][8][4];
#pragma unroll
    for (int mt = 0; mt < 2; mt++)
#pragma unroll
        for (int nt = 0; nt < 8; nt++)
#pragma unroll
            for (int e = 0; e < 4; e++) acc[mt][nt][e] = 0.0f;

    const int physLane = lane ^ ((lane >> 3) & 1);
    const int nk = K / 16;

    ldg(0);
    store_stage(0);
    __syncthreads();

    for (int i = 0; i < nk; i++) {
        const int cur = i & 1;
        const bool more = (i + 1) < nk;
        if (more) ldg((i + 1) * 16);

        const uint32_t* sb = sm + cur * STG;
        uint32_t aHi[2][4], aLo[2][4];
#pragma unroll
        for (int mt = 0; mt < 2; mt++) {
            const uint32_t* ap = sb + (warpM * 2 + mt) * F16_A_TILE + physLane * 4;
            *(uint4*)aHi[mt] = *(const uint4*)ap;
            if (P3) *(uint4*)aLo[mt] = *(const uint4*)(ap + OFF_ALO);
        }
#pragma unroll
        for (int h = 0; h < 2; h++) {
            uint32_t bHi[4][2], bLo[4][2];
#pragma unroll
            for (int n4 = 0; n4 < 4; n4++) {
                const uint32_t* bp = sb + OFF_BHI + (warpN * 8 + h * 4 + n4) * F16_B_TILE + lane * 2;
                *(uint2*)bHi[n4] = *(const uint2*)bp;
                if (P3) *(uint2*)bLo[n4] = *(const uint2*)(bp + (OFF_BLO - OFF_BHI));
            }
#pragma unroll
            for (int mt = 0; mt < 2; mt++)
#pragma unroll
                for (int n4 = 0; n4 < 4; n4++) {
                    float* c = acc[mt][h * 4 + n4];
                    mma_f16(c, aHi[mt], bHi[n4]);
                    if (P3) {
                        mma_f16(c, aHi[mt], bLo[n4]);
                        mma_f16(c, aLo[mt], bHi[n4]);
                    }
                }
        }

        if (more) store_stage(cur ^ 1);
        __syncthreads();
    }

    // epilogue
    const int gID = lane >> 2, tig = lane & 3;
#pragma unroll
    for (int mt = 0; mt < 2; mt++) {
        const int rr = rowBase + warpM * 32 + mt * 16 + gID;
#pragma unroll
        for (int nt = 0; nt < 8; nt++) {
            const int col = colBase + warpN * 64 + nt * 8 + tig * 2;
            float b0 = bias ? bias[col] : 0.f;
            float b1 = bias ? bias[col + 1] : 0.f;
            float2 o0 = {acc[mt][nt][0] * scale + b0, acc[mt][nt][1] * scale + b1};
            float2 o1 = {acc[mt][nt][2] * scale + b0, acc[mt][nt][3] * scale + b1};
            *(float2*)(C + (size_t)rr * ldc + col) = o0;
            *(float2*)(C + (size_t)(rr + 8) * ldc + col) = o1;
        }
    }
}

// host-side smem sizes (mirror template math)
#define F16_STG3 (2 * 8 * F16_A_TILE + 2 * 16 * F16_B_TILE)   // 4288 words
#define F16_STG1 (8 * F16_A_TILE + 16 * F16_B_TILE)           // 2144 words
#define SMEM3 (2 * F16_STG3 * 4)                              // 34304 B
#define SMEM1 (2 * F16_STG1 * 4)                              // 17152 B

// ------------------------- transpose (K-major prep) ------------------------
__global__ void transpose_k(const float* __restrict__ in, float* __restrict__ out,
                            int R, int C, long long sIn, long long sOut) {
    __shared__ float t[32][33];
    in  += (long long)blockIdx.z * sIn;
    out += (long long)blockIdx.z * sOut;
    const int c0 = blockIdx.x * 32, r0 = blockIdx.y * 32;
#pragma unroll
    for (int i = 0; i < 4; i++)
        t[threadIdx.y + i * 8][threadIdx.x] =
            in[(size_t)(r0 + threadIdx.y + i * 8) * C + c0 + threadIdx.x];
    __syncthreads();
#pragma unroll
    for (int i = 0; i < 4; i++)
        out[(size_t)(c0 + threadIdx.y + i * 8) * R + r0 + threadIdx.x] =
            t[threadIdx.x][threadIdx.y + i * 8];
}

// ------------------------------- softmax -----------------------------------
__global__ void softmax_rows(float* __restrict__ S, int ncols) {
    float* row = S + (size_t)blockIdx.x * ncols;
    const int tid = threadIdx.x;
    __shared__ float red[8];

    float m = -3.402823466e38f;
    for (int c = tid; c < ncols; c += 256) m = fmaxf(m, row[c]);
#pragma unroll
    for (int o = 16; o > 0; o >>= 1) m = fmaxf(m, __shfl_xor_sync(0xffffffffu, m, o));
    if ((tid & 31) == 0) red[tid >> 5] = m;
    __syncthreads();
    m = red[0];
#pragma unroll
    for (int i = 1; i < 8; i++) m = fmaxf(m, red[i]);

    float s = 0.0f;
    for (int c = tid; c < ncols; c += 256) {
        float e = expf(row[c] - m);
        row[c] = e;
        s += e;
    }
#pragma unroll
    for (int o = 16; o > 0; o >>= 1) s += __shfl_xor_sync(0xffffffffu, s, o);
    __syncthreads();
    if ((tid & 31) == 0) red[tid >> 5] = s;
    __syncthreads();
    s = 0.0f;
#pragma unroll
    for (int i = 0; i < 8; i++) s += red[i];
    const float inv = 1.0f / s;
    for (int c = tid; c < ncols; c += 256) row[c] *= inv;
}

// ------------------------------- launcher ----------------------------------
extern "C" void kernel_launch(void* const* d_in, const int* in_sizes, int n_in,
                              void* d_out, int out_size) {
    const float* q  = (const float*)d_in[0];
    const float* k  = (const float*)d_in[1];
    const float* v  = (const float*)d_in[2];
    const float* Wq = (const float*)d_in[3];
    const float* Wk = (const float*)d_in[4];
    const float* Wv = (const float*)d_in[5];
    const float* bq = (const float*)d_in[6];
    const float* bk = (const float*)d_in[7];
    const float* bv = (const float*)d_in[8];
    float* out = (float*)d_out;

    float *Qp, *Kp, *Vp, *Vtp, *Sp, *Wtp;
    cudaGetSymbolAddress((void**)&Qp,  g_Q);
    cudaGetSymbolAddress((void**)&Kp,  g_K);
    cudaGetSymbolAddress((void**)&Vp,  g_V);
    cudaGetSymbolAddress((void**)&Vtp, g_Vt);
    cudaGetSymbolAddress((void**)&Sp,  g_S);
    cudaGetSymbolAddress((void**)&Wtp, g_Wt);

    static int smem_set = 0;
    if (!smem_set) {
        cudaFuncSetAttribute(gemm_f16<3>, cudaFuncAttributeMaxDynamicSharedMemorySize, SMEM3);
        cudaFuncSetAttribute(gemm_f16<1>, cudaFuncAttributeMaxDynamicSharedMemorySize, SMEM1);
        smem_set = 1;
    }

    const dim3 tthr(32, 8);

    // 1) projections (Wt = W^T, K-major)
    dim3 gproj(MODEL / BN, MTOT / BM, 1);           // (8, 64)
    transpose_k<<<dim3(32, 32, 1), tthr>>>(Wq, Wtp, MODEL, MODEL, 0, 0);
    gemm_f16<3><<<gproj, NTHREADS, SMEM3>>>(q, MODEL, Wtp, MODEL, Qp, MODEL, bq, 1.0f, MODEL, 0, 0, 0);
    transpose_k<<<dim3(32, 32, 1), tthr>>>(Wk, Wtp, MODEL, MODEL, 0, 0);
    gemm_f16<3><<<gproj, NTHREADS, SMEM3>>>(k, MODEL, Wtp, MODEL, Kp, MODEL, bk, 1.0f, MODEL, 0, 0, 0);
    transpose_k<<<dim3(32, 32, 1), tthr>>>(Wv, Wtp, MODEL, MODEL, 0, 0);
    gemm_f16<1><<<gproj, NTHREADS, SMEM1>>>(v, MODEL, Wtp, MODEL, Vp, MODEL, bv, 1.0f, MODEL, 0, 0, 0);

    // 2) scores: S[b] = (Q[b] @ K[b]^T) / 32
    dim3 gsc(SEQ / BN, SEQ / BM, BATCH);            // (16, 16, 4)
    gemm_f16<3><<<gsc, NTHREADS, SMEM3>>>(Qp, MODEL, Kp, MODEL, Sp, SEQ, nullptr, 0.03125f,
                                          MODEL, (long long)SEQ * MODEL, (long long)SEQ * MODEL,
                                          (long long)SEQ * SEQ);

    // 3) softmax rows
    softmax_rows<<<BATCH * SEQ, 256>>>(Sp, SEQ);

    // 4) Vt[b] = V[b]^T
    transpose_k<<<dim3(MODEL / 32, SEQ / 32, BATCH), tthr>>>(Vp, Vtp, SEQ, MODEL,
                                                             (long long)SEQ * MODEL,
                                                             (long long)SEQ * MODEL);

    // 5) O[b] = P[b] @ Vt[b]^T  (single-pass fp16)
    dim3 gpv(MODEL / BN, SEQ / BM, BATCH);          // (8, 16, 4)
    gemm_f16<1><<<gpv, NTHREADS, SMEM1>>>(Sp, SEQ, Vtp, SEQ, out, MODEL, nullptr, 1.0f,
                                          SEQ, (long long)SEQ * SEQ, (long long)SEQ * MODEL,
                                          (long long)SEQ * MODEL);
}

// round 8
// speedup vs baseline: 3.3097x; 1.1350x over previous
#include <cuda_runtime.h>
#include <cuda_fp16.h>
#include <cstdint>
#include <math.h>

// ---------------------------------------------------------------------------
// DotProductAttention (sm_103 plain -> mma.sync m16n8k16 fp16).
// Projections write hi/lo fp16 planes in mma-fragment-tile order; scores/PV
// GEMMs stage by pure memcpy (no cvt in hot loops).
// Q/K proj + scores: 3-term hi/lo split (fp32-grade). V proj + PV: 1-pass.
// R8: fix vt_frag shared-memory uint4 alignment (stride 33 -> 36).
// ---------------------------------------------------------------------------

#define BATCH 4
#define SEQ   2048
#define MODEL 1024
#define MTOT  (BATCH * SEQ)   // 8192

// fragment-tile planes (u32 = half2)
__device__ uint32_t g_QH[(size_t)MTOT * MODEL / 2];
__device__ uint32_t g_QL[(size_t)MTOT * MODEL / 2];
__device__ uint32_t g_KH[(size_t)MTOT * MODEL / 2];
__device__ uint32_t g_KL[(size_t)MTOT * MODEL / 2];
__device__ uint32_t g_Vh[(size_t)MTOT * MODEL / 2];                 // row-major half2
__device__ uint32_t g_VT[(size_t)BATCH * (MODEL / 8) * (SEQ / 16) * 64];
__device__ uint32_t g_P [(size_t)MTOT * (SEQ / 2)];
__device__ float    g_S [(size_t)BATCH * SEQ * SEQ];
__device__ float    g_Wt[MODEL * MODEL];

#define NTHREADS 256

__device__ __forceinline__ void f16_split2(float a, float b, uint32_t& hi, uint32_t& lo) {
    __half ha = __float2half_rn(a), hb = __float2half_rn(b);
    __half la = __float2half_rn(a - __half2float(ha));
    __half lb = __float2half_rn(b - __half2float(hb));
    hi = ((uint32_t)__half_as_ushort(hb) << 16) | (uint32_t)__half_as_ushort(ha);
    lo = ((uint32_t)__half_as_ushort(lb) << 16) | (uint32_t)__half_as_ushort(la);
}
__device__ __forceinline__ uint32_t f16_pack2(float a, float b) {
    __half ha = __float2half_rn(a), hb = __float2half_rn(b);
    return ((uint32_t)__half_as_ushort(hb) << 16) | (uint32_t)__half_as_ushort(ha);
}
__device__ __forceinline__ void mma_f16(float* c, const uint32_t* a, const uint32_t* b) {
    asm volatile(
        "mma.sync.aligned.m16n8k16.row.col.f32.f16.f16.f32 "
        "{%0,%1,%2,%3}, {%4,%5,%6,%7}, {%8,%9}, {%0,%1,%2,%3};"
        : "+f"(c[0]), "+f"(c[1]), "+f"(c[2]), "+f"(c[3])
        : "r"(a[0]), "r"(a[1]), "r"(a[2]), "r"(a[3]), "r"(b[0]), "r"(b[1]));
}

// ===================== projection GEMM (fp32 in, planes out) ===============
// EPI: 1 = A-frag hi/lo planes, 2 = B-frag hi/lo planes, 3 = half row-major
#define F16_A_TILE 132
#define F16_B_TILE 68
#define PROJ_STG3 (2 * 8 * F16_A_TILE + 2 * 16 * F16_B_TILE)   // 4288 words
#define PROJ_STG1 (8 * F16_A_TILE + 16 * F16_B_TILE)           // 2144 words
#define PROJ_SMEM3 (2 * PROJ_STG3 * 4)
#define PROJ_SMEM1 (2 * PROJ_STG1 * 4)

template <int PASSES, int EPI>
__global__ void __launch_bounds__(NTHREADS, 2) gemm_proj(
    const float* __restrict__ A,
    const float* __restrict__ B,
    const float* __restrict__ bias,
    uint32_t* __restrict__ PH, uint32_t* __restrict__ PL, int nktOut)
{
    constexpr bool P3 = (PASSES == 3);
    constexpr int NA = P3 ? 2 : 1;
    constexpr int OFF_ALO = 8 * F16_A_TILE;
    constexpr int OFF_BHI = NA * 8 * F16_A_TILE;
    constexpr int OFF_BLO = OFF_BHI + 16 * F16_B_TILE;
    constexpr int STG = OFF_BHI + NA * 16 * F16_B_TILE;

    extern __shared__ uint32_t sm[];
    const int tid = threadIdx.x;
    const int wid = tid >> 5, lane = tid & 31;
    const int warpM = wid & 3;
    const int warpN = wid >> 2;
    const int rowBase = blockIdx.y * 128;
    const int colBase = blockIdx.x * 128;

    const int r0 = tid >> 2, qc = tid & 3;
    const int lane0 = ((r0 & 7) << 2) + ((qc & 1) << 1);
    const int p0 = lane0 ^ ((lane0 >> 3) & 1);
    const int p1 = (lane0 + 1) ^ (((lane0 + 1) >> 3) & 1);
    const int regA = ((r0 >> 3) & 1) | (qc & 2);
    const int regB = (qc >> 1) & 1;

    float4 pA0, pA1, pB0, pB1;
    auto ldg = [&](int kt) {
        pA0 = *(const float4*)(A + (size_t)(rowBase + r0) * MODEL + kt + qc * 4);
        pA1 = *(const float4*)(A + (size_t)(rowBase + r0 + 64) * MODEL + kt + qc * 4);
        pB0 = *(const float4*)(B + (size_t)(colBase + r0) * MODEL + kt + qc * 4);
        pB1 = *(const float4*)(B + (size_t)(colBase + r0 + 64) * MODEL + kt + qc * 4);
    };
    auto store_stage = [&](int stg) {
        uint32_t* base = sm + stg * STG;
        const float4 av[2] = {pA0, pA1};
        const float4 bv[2] = {pB0, pB1};
#pragma unroll
        for (int j = 0; j < 2; j++) {
            const int r = r0 + j * 64;
            {
                uint32_t* th = base + (r >> 4) * F16_A_TILE;
                if (P3) {
                    uint32_t* tl = th + OFF_ALO;
                    uint32_t h0, l0, h1, l1;
                    f16_split2(av[j].x, av[j].y, h0, l0);
                    f16_split2(av[j].z, av[j].w, h1, l1);
                    th[p0 * 4 + regA] = h0; th[p1 * 4 + regA] = h1;
                    tl[p0 * 4 + regA] = l0; tl[p1 * 4 + regA] = l1;
                } else {
                    th[p0 * 4 + regA] = f16_pack2(av[j].x, av[j].y);
                    th[p1 * 4 + regA] = f16_pack2(av[j].z, av[j].w);
                }
            }
            {
                uint32_t* th = base + OFF_BHI + (r >> 3) * F16_B_TILE;
                if (P3) {
                    uint32_t* tl = th + (OFF_BLO - OFF_BHI);
                    uint32_t h0, l0, h1, l1;
                    f16_split2(bv[j].x, bv[j].y, h0, l0);
                    f16_split2(bv[j].z, bv[j].w, h1, l1);
                    th[lane0 * 2 + regB] = h0; th[(lane0 + 1) * 2 + regB] = h1;
                    tl[lane0 * 2 + regB] = l0; tl[(lane0 + 1) * 2 + regB] = l1;
                } else {
                    th[lane0 * 2 + regB] = f16_pack2(bv[j].x, bv[j].y);
                    th[(lane0 + 1) * 2 + regB] = f16_pack2(bv[j].z, bv[j].w);
                }
            }
        }
    };

    float acc[2][8][4];
#pragma unroll
    for (int mt = 0; mt < 2; mt++)
#pragma unroll
        for (int nt = 0; nt < 8; nt++)
#pragma unroll
            for (int e = 0; e < 4; e++) acc[mt][nt][e] = 0.0f;

    const int physLane = lane ^ ((lane >> 3) & 1);
    const int nk = MODEL / 16;

    ldg(0);
    store_stage(0);
    __syncthreads();

    for (int i = 0; i < nk; i++) {
        const int cur = i & 1;
        const bool more = (i + 1) < nk;
        if (more) ldg((i + 1) * 16);

        const uint32_t* sb = sm + cur * STG;
        uint32_t aHi[2][4], aLo[2][4];
#pragma unroll
        for (int mt = 0; mt < 2; mt++) {
            const uint32_t* ap = sb + (warpM * 2 + mt) * F16_A_TILE + physLane * 4;
            *(uint4*)aHi[mt] = *(const uint4*)ap;
            if (P3) *(uint4*)aLo[mt] = *(const uint4*)(ap + OFF_ALO);
        }
#pragma unroll
        for (int h = 0; h < 2; h++) {
            uint32_t bHi[4][2], bLo[4][2];
#pragma unroll
            for (int n4 = 0; n4 < 4; n4++) {
                const uint32_t* bp = sb + OFF_BHI + (warpN * 8 + h * 4 + n4) * F16_B_TILE + lane * 2;
                *(uint2*)bHi[n4] = *(const uint2*)bp;
                if (P3) *(uint2*)bLo[n4] = *(const uint2*)(bp + (OFF_BLO - OFF_BHI));
            }
#pragma unroll
            for (int mt = 0; mt < 2; mt++)
#pragma unroll
                for (int n4 = 0; n4 < 4; n4++) {
                    float* c = acc[mt][h * 4 + n4];
                    mma_f16(c, aHi[mt], bHi[n4]);
                    if (P3) { mma_f16(c, aHi[mt], bLo[n4]); mma_f16(c, aLo[mt], bHi[n4]); }
                }
        }
        if (more) store_stage(cur ^ 1);
        __syncthreads();
    }

    // ---- epilogue: write planes ----
    const int gID = lane >> 2, tig = lane & 3;
#pragma unroll
    for (int mt = 0; mt < 2; mt++) {
        const int r = rowBase + warpM * 32 + mt * 16 + gID;   // bit3 of r is 0
#pragma unroll
        for (int nt = 0; nt < 8; nt++) {
            const int c = colBase + warpN * 64 + nt * 8 + tig * 2;
            const float b0 = bias[c], b1 = bias[c + 1];
            const float v00 = acc[mt][nt][0] + b0, v01 = acc[mt][nt][1] + b1;
            const float v10 = acc[mt][nt][2] + b0, v11 = acc[mt][nt][3] + b1;
            const int p = (c & 15) >> 1;
            if (EPI == 1) {
                const int lfr = (((r & 7)) << 2) | (p & 3);
                const int rg0 = (p >> 2) << 1;
                const size_t tb = ((size_t)(r >> 4) * nktOut + (c >> 4)) * 128 + lfr * 4 + rg0;
                uint32_t h0, l0, h1, l1;
                f16_split2(v00, v01, h0, l0);
                f16_split2(v10, v11, h1, l1);
                uint2 uh = {h0, h1}, ul = {l0, l1};
                *(uint2*)(PH + tb) = uh;
                *(uint2*)(PL + tb) = ul;
            } else if (EPI == 2) {
                const int lfr = ((r & 7) << 2) | (p & 3);
                const int rg = p >> 2;
                const size_t tb0 = ((size_t)(r >> 3) * nktOut + (c >> 4)) * 64 + lfr * 2 + rg;
                const size_t tb1 = ((size_t)((r + 8) >> 3) * nktOut + (c >> 4)) * 64 + lfr * 2 + rg;
                uint32_t h0, l0, h1, l1;
                f16_split2(v00, v01, h0, l0);
                f16_split2(v10, v11, h1, l1);
                PH[tb0] = h0; PH[tb1] = h1;
                PL[tb0] = l0; PL[tb1] = l1;
            } else {  // EPI 3: half row-major plane (width MODEL/2 u32)
                PH[(size_t)r * (MODEL / 2) + (c >> 1)] = f16_pack2(v00, v01);
                PH[(size_t)(r + 8) * (MODEL / 2) + (c >> 1)] = f16_pack2(v10, v11);
            }
        }
    }
}

// ================= plane-in GEMM (fp16 fragment tiles -> fp32) =============
template <int PASSES>
__global__ void __launch_bounds__(NTHREADS, 2) gemm_h(
    const uint32_t* __restrict__ AH, const uint32_t* __restrict__ AL, int nktA,
    const uint32_t* __restrict__ BH, const uint32_t* __restrict__ BL, int nktB,
    float* __restrict__ C, int ldc, float scale, int nk,
    int mtZ, int ntZ, long long sC)
{
    constexpr bool P3 = (PASSES == 3);
    constexpr int NA = P3 ? 2 : 1;
    constexpr int OFF_B = NA * 1024;
    constexpr int STG = NA * 2048;

    extern __shared__ uint32_t sm[];
    const int tid = threadIdx.x;
    const int wid = tid >> 5, lane = tid & 31;
    const int warpM = wid & 3;
    const int warpN = wid >> 2;

    const int z = blockIdx.z;
    const int mtBase = z * mtZ + blockIdx.y * 8;
    const int ntBase = z * ntZ + blockIdx.x * 16;
    const int rowBase = blockIdx.y * 128;
    const int colBase = blockIdx.x * 128;
    C += (long long)z * sC;

    const int tA = tid >> 5, wA = (tid & 31) * 4;
    const int tB = tid >> 4, wB = (tid & 15) * 4;
    const uint32_t* gAH = AH + (size_t)(mtBase + tA) * nktA * 128 + wA;
    const uint32_t* gAL = P3 ? (AL + (size_t)(mtBase + tA) * nktA * 128 + wA) : nullptr;
    const uint32_t* gBH = BH + (size_t)(ntBase + tB) * nktB * 64 + wB;
    const uint32_t* gBL = P3 ? (BL + (size_t)(ntBase + tB) * nktB * 64 + wB) : nullptr;

    uint4 rAH, rAL, rBH, rBL;
    auto ldg = [&](int kt) {
        rAH = *(const uint4*)(gAH + (size_t)kt * 128);
        if (P3) rAL = *(const uint4*)(gAL + (size_t)kt * 128);
        rBH = *(const uint4*)(gBH + (size_t)kt * 64);
        if (P3) rBL = *(const uint4*)(gBL + (size_t)kt * 64);
    };
    auto store_stage = [&](int stg) {
        uint32_t* s = sm + stg * STG;
        *(uint4*)(s + tid * 4) = rAH;
        if (P3) *(uint4*)(s + 1024 + tid * 4) = rAL;
        *(uint4*)(s + OFF_B + tid * 4) = rBH;
        if (P3) *(uint4*)(s + OFF_B + 1024 + tid * 4) = rBL;
    };

    float acc[2][8][4];
#pragma unroll
    for (int mt = 0; mt < 2; mt++)
#pragma unroll
        for (int nt = 0; nt < 8; nt++)
#pragma unroll
            for (int e = 0; e < 4; e++) acc[mt][nt][e] = 0.0f;

    ldg(0);
    store_stage(0);
    __syncthreads();

    for (int i = 0; i < nk; i++) {
        const int cur = i & 1;
        const bool more = (i + 1) < nk;
        if (more) ldg(i + 1);

        const uint32_t* sb = sm + cur * STG;
        uint32_t aHi[2][4], aLo[2][4];
#pragma unroll
        for (int mt = 0; mt < 2; mt++) {
            const uint32_t* ap = sb + (warpM * 2 + mt) * 128 + lane * 4;
            *(uint4*)aHi[mt] = *(const uint4*)ap;
            if (P3) *(uint4*)aLo[mt] = *(const uint4*)(ap + 1024);
        }
#pragma unroll
        for (int h = 0; h < 2; h++) {
            uint32_t bHi[4][2], bLo[4][2];
#pragma unroll
            for (int n4 = 0; n4 < 4; n4++) {
                const uint32_t* bp = sb + OFF_B + (warpN * 8 + h * 4 + n4) * 64 + lane * 2;
                *(uint2*)bHi[n4] = *(const uint2*)bp;
                if (P3) *(uint2*)bLo[n4] = *(const uint2*)(bp + 1024);
            }
#pragma unroll
            for (int mt = 0; mt < 2; mt++)
#pragma unroll
                for (int n4 = 0; n4 < 4; n4++) {
                    float* c = acc[mt][h * 4 + n4];
                    mma_f16(c, aHi[mt], bHi[n4]);
                    if (P3) { mma_f16(c, aHi[mt], bLo[n4]); mma_f16(c, aLo[mt], bHi[n4]); }
                }
        }
        if (more) store_stage(cur ^ 1);
        __syncthreads();
    }

    const int gID = lane >> 2, tig = lane & 3;
#pragma unroll
    for (int mt = 0; mt < 2; mt++) {
        const int r = rowBase + warpM * 32 + mt * 16 + gID;
#pragma unroll
        for (int nt = 0; nt < 8; nt++) {
            const int c = colBase + warpN * 64 + nt * 8 + tig * 2;
            float2 o0 = {acc[mt][nt][0] * scale, acc[mt][nt][1] * scale};
            float2 o1 = {acc[mt][nt][2] * scale, acc[mt][nt][3] * scale};
            *(float2*)(C + (size_t)r * ldc + c) = o0;
            *(float2*)(C + (size_t)(r + 8) * ldc + c) = o1;
        }
    }
}

// ================ softmax: fp32 S row -> fp16 A-frag P plane ===============
__global__ void softmax_p(const float* __restrict__ S, uint32_t* __restrict__ P) {
    const int s = blockIdx.x;                   // global row 0..MTOT-1
    const float* row = S + (size_t)s * SEQ;
    const int tid = threadIdx.x;
    __shared__ float red[8];

    float x[8];
#pragma unroll
    for (int j = 0; j < 4; j++) {
        float2 v = *(const float2*)(row + 2 * (tid + j * 256));
        x[2 * j] = v.x;
        x[2 * j + 1] = v.y;
    }
    float m = x[0];
#pragma unroll
    for (int i = 1; i < 8; i++) m = fmaxf(m, x[i]);
#pragma unroll
    for (int o = 16; o > 0; o >>= 1) m = fmaxf(m, __shfl_xor_sync(0xffffffffu, m, o));
    if ((tid & 31) == 0) red[tid >> 5] = m;
    __syncthreads();
    m = red[0];
#pragma unroll
    for (int i = 1; i < 8; i++) m = fmaxf(m, red[i]);
    __syncthreads();

    float e[8], ssum = 0.0f;
#pragma unroll
    for (int i = 0; i < 8; i++) { e[i] = expf(x[i] - m); ssum += e[i]; }
#pragma unroll
    for (int o = 16; o > 0; o >>= 1) ssum += __shfl_xor_sync(0xffffffffu, ssum, o);
    if ((tid & 31) == 0) red[tid >> 5] = ssum;
    __syncthreads();
    ssum = 0.0f;
#pragma unroll
    for (int i = 0; i < 8; i++) ssum += red[i];
    const float inv = 1.0f / ssum;

    const int laneRow = (s & 7) << 2;
    const int regRow = (s >> 3) & 1;
    const size_t mtOff = (size_t)(s >> 4) * 128;
#pragma unroll
    for (int j = 0; j < 4; j++) {
        const int cp = tid + j * 256;           // pair index 0..1023
        const int pl = cp & 7, kt = cp >> 3;
        const int lfr = laneRow | (pl & 3);
        const int rg = regRow | ((pl >> 2) << 1);
        P[(mtOff + kt) * 128 + lfr * 4 + rg] = f16_pack2(e[2 * j] * inv, e[2 * j + 1] * inv);
    }
}

// ============ V half plane (row-major) -> VT B-frag tiles ==================
__global__ void vt_frag(const uint32_t* __restrict__ Vh, uint32_t* __restrict__ VT) {
    __shared__ uint32_t smv[64][36];            // stride 36: keeps uint4 16B-aligned
    const int z = blockIdx.z;
    const int t0 = blockIdx.y * 64, d0 = blockIdx.x * 64;
    const int tr = threadIdx.x >> 3, dq = threadIdx.x & 7;
#pragma unroll
    for (int i = 0; i < 2; i++) {
        const int t = tr + i * 32;
        *(uint4*)&smv[t][dq * 4] =
            *(const uint4*)(Vh + (size_t)(z * SEQ + t0 + t) * (MODEL / 2) + (d0 >> 1) + dq * 4);
    }
    __syncthreads();
#pragma unroll
    for (int i = 0; i < 8; i++) {
        const int idx = threadIdx.x + i * 256;  // 0..2047
        const int tile = idx >> 6, within = idx & 63;
        const int lfr = within >> 1, rg = within & 1;
        const int ntl = tile >> 2, ktl = tile & 3;
        const int n = ntl * 8 + (lfr >> 2);
        const int p = (lfr & 3) | (rg << 2);
        const int k = ktl * 16 + p * 2;
        const uint32_t a = smv[k][n >> 1], b = smv[k + 1][n >> 1];
        const uint32_t h0 = (n & 1) ? (a >> 16) : (a & 0xffffu);
        const uint32_t h1 = (n & 1) ? (b >> 16) : (b & 0xffffu);
        VT[((size_t)(z * 128 + (d0 >> 3) + ntl) * 128 + (t0 >> 4) + ktl) * 64 + within] =
            h0 | (h1 << 16);
    }
}

// ------------------------- transpose (W prep, fp32) ------------------------
__global__ void transpose_k(const float* __restrict__ in, float* __restrict__ out,
                            int R, int C) {
    __shared__ float t[32][33];
    const int c0 = blockIdx.x * 32, r0 = blockIdx.y * 32;
#pragma unroll
    for (int i = 0; i < 4; i++)
        t[threadIdx.y + i * 8][threadIdx.x] =
            in[(size_t)(r0 + threadIdx.y + i * 8) * C + c0 + threadIdx.x];
    __syncthreads();
#pragma unroll
    for (int i = 0; i < 4; i++)
        out[(size_t)(c0 + threadIdx.y + i * 8) * R + r0 + threadIdx.x] =
            t[threadIdx.x][threadIdx.y + i * 8];
}

// ------------------------------- launcher ----------------------------------
extern "C" void kernel_launch(void* const* d_in, const int* in_sizes, int n_in,
                              void* d_out, int out_size) {
    const float* q  = (const float*)d_in[0];
    const float* k  = (const float*)d_in[1];
    const float* v  = (const float*)d_in[2];
    const float* Wq = (const float*)d_in[3];
    const float* Wk = (const float*)d_in[4];
    const float* Wv = (const float*)d_in[5];
    const float* bq = (const float*)d_in[6];
    const float* bk = (const float*)d_in[7];
    const float* bv = (const float*)d_in[8];
    float* out = (float*)d_out;

    uint32_t *QH, *QL, *KH, *KL, *Vh, *VT, *P;
    float *Sp, *Wtp;
    cudaGetSymbolAddress((void**)&QH, g_QH);
    cudaGetSymbolAddress((void**)&QL, g_QL);
    cudaGetSymbolAddress((void**)&KH, g_KH);
    cudaGetSymbolAddress((void**)&KL, g_KL);
    cudaGetSymbolAddress((void**)&Vh, g_Vh);
    cudaGetSymbolAddress((void**)&VT, g_VT);
    cudaGetSymbolAddress((void**)&P,  g_P);
    cudaGetSymbolAddress((void**)&Sp, g_S);
    cudaGetSymbolAddress((void**)&Wtp, g_Wt);

    const dim3 tthr(32, 8);
    const dim3 gproj(MODEL / 128, MTOT / 128, 1);   // (8, 64)

    // 1) projections -> fragment planes
    transpose_k<<<dim3(32, 32), tthr>>>(Wq, Wtp, MODEL, MODEL);
    gemm_proj<3, 1><<<gproj, NTHREADS, PROJ_SMEM3>>>(q, Wtp, bq, QH, QL, MODEL / 16);
    transpose_k<<<dim3(32, 32), tthr>>>(Wk, Wtp, MODEL, MODEL);
    gemm_proj<3, 2><<<gproj, NTHREADS, PROJ_SMEM3>>>(k, Wtp, bk, KH, KL, MODEL / 16);
    transpose_k<<<dim3(32, 32), tthr>>>(Wv, Wtp, MODEL, MODEL);
    gemm_proj<1, 3><<<gproj, NTHREADS, PROJ_SMEM1>>>(v, Wtp, bv, Vh, nullptr, 0);

    // 2) scores: S = (Q K^T) / 32   (3-pass, plane-in)
    dim3 gsc(SEQ / 128, SEQ / 128, BATCH);          // (16, 16, 4)
    gemm_h<3><<<gsc, NTHREADS, 2 * 4096 * 4>>>(QH, QL, MODEL / 16, KH, KL, MODEL / 16,
                                               Sp, SEQ, 0.03125f, MODEL / 16,
                                               128, 256, (long long)SEQ * SEQ);

    // 3) softmax -> P fp16 A-frag plane
    softmax_p<<<MTOT, 256>>>(Sp, P);

    // 4) V half plane -> VT B-frag tiles
    vt_frag<<<dim3(MODEL / 64, SEQ / 64, BATCH), 256>>>(Vh, VT);

    // 5) O = P V  (1-pass, plane-in)
    dim3 gpv(MODEL / 128, SEQ / 128, BATCH);        // (8, 16, 4)
    gemm_h<1><<<gpv, NTHREADS, 2 * 2048 * 4>>>(P, nullptr, SEQ / 16, VT, nullptr, SEQ / 16,
                                               out, MODEL, 1.0f, SEQ / 16,
                                               128, 128, (long long)SEQ * MODEL);
}

// round 9
// speedup vs baseline: 3.9527x; 1.1943x over previous
#include <cuda_runtime.h>
#include <cuda_fp16.h>
#include <cstdint>
#include <math.h>

// ---------------------------------------------------------------------------
// DotProductAttention (sm_103 plain -> mma.sync m16n8k16 fp16).
// R9: all operands pre-split into fragment-order hi/lo planes; unified GEMM
// with 64x64 warp tiles (24 MAC/smem-byte) + cp.async double buffering.
// Q/K proj + scores: 3-term hi/lo split. V proj + PV: 1-pass fp16.
// ---------------------------------------------------------------------------

#define BATCH 4
#define SEQ   2048
#define MODEL 1024
#define MTOT  (BATCH * SEQ)   // 8192

// pre-split input planes
__device__ uint32_t g_qAH[(size_t)MTOT * MODEL / 2];
__device__ uint32_t g_qAL[(size_t)MTOT * MODEL / 2];
__device__ uint32_t g_kAH[(size_t)MTOT * MODEL / 2];
__device__ uint32_t g_kAL[(size_t)MTOT * MODEL / 2];
__device__ uint32_t g_vAH[(size_t)MTOT * MODEL / 2];
__device__ uint32_t g_WqH[MODEL * MODEL / 2];
__device__ uint32_t g_WqL[MODEL * MODEL / 2];
__device__ uint32_t g_WkH[MODEL * MODEL / 2];
__device__ uint32_t g_WkL[MODEL * MODEL / 2];
__device__ uint32_t g_WvH[MODEL * MODEL / 2];
// projected planes
__device__ uint32_t g_QH[(size_t)MTOT * MODEL / 2];
__device__ uint32_t g_QL[(size_t)MTOT * MODEL / 2];
__device__ uint32_t g_KH[(size_t)MTOT * MODEL / 2];
__device__ uint32_t g_KL[(size_t)MTOT * MODEL / 2];
__device__ uint32_t g_Vh[(size_t)MTOT * MODEL / 2];   // row-major half2
__device__ uint32_t g_VT[(size_t)BATCH * (MODEL / 8) * (SEQ / 16) * 64];
__device__ uint32_t g_P [(size_t)MTOT * (SEQ / 2)];
__device__ float    g_S [(size_t)BATCH * SEQ * SEQ];

__device__ __forceinline__ void f16_split2(float a, float b, uint32_t& hi, uint32_t& lo) {
    __half ha = __float2half_rn(a), hb = __float2half_rn(b);
    __half la = __float2half_rn(a - __half2float(ha));
    __half lb = __float2half_rn(b - __half2float(hb));
    hi = ((uint32_t)__half_as_ushort(hb) << 16) | (uint32_t)__half_as_ushort(ha);
    lo = ((uint32_t)__half_as_ushort(lb) << 16) | (uint32_t)__half_as_ushort(la);
}
__device__ __forceinline__ uint32_t f16_pack2(float a, float b) {
    __half ha = __float2half_rn(a), hb = __float2half_rn(b);
    return ((uint32_t)__half_as_ushort(hb) << 16) | (uint32_t)__half_as_ushort(ha);
}
__device__ __forceinline__ void mma_f16(float* c, const uint32_t* a, const uint32_t* b) {
    asm volatile(
        "mma.sync.aligned.m16n8k16.row.col.f32.f16.f16.f32 "
        "{%0,%1,%2,%3}, {%4,%5,%6,%7}, {%8,%9}, {%0,%1,%2,%3};"
        : "+f"(c[0]), "+f"(c[1]), "+f"(c[2]), "+f"(c[3])
        : "r"(a[0]), "r"(a[1]), "r"(a[2]), "r"(a[3]), "r"(b[0]), "r"(b[1]));
}
__device__ __forceinline__ void cp16(uint32_t s, const void* g) {
    asm volatile("cp.async.cg.shared.global [%0], [%1], 16;" :: "r"(s), "l"(g));
}
__device__ __forceinline__ void cp_commit() { asm volatile("cp.async.commit_group;" ::: "memory"); }
template <int N> __device__ __forceinline__ void cp_wait() {
    asm volatile("cp.async.wait_group %0;" :: "n"(N) : "memory");
}

// ================= unified plane-in GEMM, warp tile 64x64 ==================
// EPI: 0 = fp32 C, 1 = A-frag hi/lo planes, 2 = B-frag hi/lo planes,
//      3 = half2 row-major plane
template <int PASSES, int EPI>
__global__ void __launch_bounds__(128, 2) gemm_c(
    const uint32_t* __restrict__ AH, const uint32_t* __restrict__ AL, int nktA,
    const uint32_t* __restrict__ BH, const uint32_t* __restrict__ BL, int nktB,
    uint32_t* __restrict__ OH, uint32_t* __restrict__ OL, int ldn,
    const float* __restrict__ bias, float scale, int nk,
    int mtZ, int ntZ, long long sOz)
{
    constexpr bool P3 = (PASSES == 3);
    constexpr int STG = P3 ? 4096 : 2048;       // u32 per stage
    constexpr int OFF_AL = 1024;
    constexpr int OFF_BHs = P3 ? 2048 : 1024;
    constexpr int OFF_BLs = OFF_BHs + 1024;

    extern __shared__ uint32_t sm[];
    const uint32_t sb0 = (uint32_t)__cvta_generic_to_shared(sm);
    const int tid = threadIdx.x, wid = tid >> 5, lane = tid & 31;
    const int warpM = wid & 1, warpN = wid >> 1;
    const int z = blockIdx.z;
    const int mtBase = z * mtZ + blockIdx.y * 8;
    const int ntBase = z * ntZ + blockIdx.x * 16;
    const int rowBase = blockIdx.y * 128, colBase = blockIdx.x * 128;

    int aT[2], aW[2], bT[2], bW[2];
    const uint32_t *gA[2], *gAl[2], *gB[2], *gBl[2];
#pragma unroll
    for (int g = 0; g < 2; g++) {
        const int ga = tid * 2 + g;
        aT[g] = ga >> 5; aW[g] = (ga & 31) * 4;
        bT[g] = ga >> 4; bW[g] = (ga & 15) * 4;
        gA[g] = AH + (size_t)(mtBase + aT[g]) * nktA * 128 + aW[g];
        gB[g] = BH + (size_t)(ntBase + bT[g]) * nktB * 64 + bW[g];
        if (P3) {
            gAl[g] = AL + (size_t)(mtBase + aT[g]) * nktA * 128 + aW[g];
            gBl[g] = BL + (size_t)(ntBase + bT[g]) * nktB * 64 + bW[g];
        }
    }

    auto issue = [&](int kt, int stg) {
        const uint32_t s = sb0 + stg * (STG * 4);
#pragma unroll
        for (int g = 0; g < 2; g++) {
            cp16(s + (aT[g] * 128 + aW[g]) * 4, gA[g] + (size_t)kt * 128);
            if (P3) cp16(s + (OFF_AL + aT[g] * 128 + aW[g]) * 4, gAl[g] + (size_t)kt * 128);
            cp16(s + (OFF_BHs + bT[g] * 64 + bW[g]) * 4, gB[g] + (size_t)kt * 64);
            if (P3) cp16(s + (OFF_BLs + bT[g] * 64 + bW[g]) * 4, gBl[g] + (size_t)kt * 64);
        }
        cp_commit();
    };

    float acc[4][8][4];
#pragma unroll
    for (int mt = 0; mt < 4; mt++)
#pragma unroll
        for (int nt = 0; nt < 8; nt++)
#pragma unroll
            for (int e = 0; e < 4; e++) acc[mt][nt][e] = 0.0f;

    issue(0, 0);

    for (int i = 0; i < nk; i++) {
        const int cur = i & 1;
        const bool more = (i + 1) < nk;
        if (more) { issue(i + 1, cur ^ 1); cp_wait<1>(); }
        else      { cp_wait<0>(); }
        __syncthreads();                       // peer copies visible

        const uint32_t* s = sm + cur * STG;
        uint32_t aHi[4][4], aLo[4][4];
#pragma unroll
        for (int mt = 0; mt < 4; mt++) {
            const uint32_t* ap = s + (warpM * 4 + mt) * 128 + lane * 4;
            *(uint4*)aHi[mt] = *(const uint4*)ap;
            if (P3) *(uint4*)aLo[mt] = *(const uint4*)(ap + OFF_AL);
        }
#pragma unroll
        for (int h = 0; h < 2; h++) {
            uint32_t bHi[4][2], bLo[4][2];
#pragma unroll
            for (int n4 = 0; n4 < 4; n4++) {
                const uint32_t* bp = s + OFF_BHs + (warpN * 8 + h * 4 + n4) * 64 + lane * 2;
                *(uint2*)bHi[n4] = *(const uint2*)bp;
                if (P3) *(uint2*)bLo[n4] = *(const uint2*)(bp + 1024);
            }
#pragma unroll
            for (int mt = 0; mt < 4; mt++)
#pragma unroll
                for (int n4 = 0; n4 < 4; n4++) {
                    float* c = acc[mt][h * 4 + n4];
                    mma_f16(c, aHi[mt], bHi[n4]);
                    if (P3) { mma_f16(c, aHi[mt], bLo[n4]); mma_f16(c, aLo[mt], bHi[n4]); }
                }
        }
        __syncthreads();                       // done reading before next issue
    }

    // ---- epilogue ----
    const int gID = lane >> 2, tig = lane & 3;
#pragma unroll
    for (int mt = 0; mt < 4; mt++) {
        const int r = rowBase + warpM * 64 + mt * 16 + gID;    // bit3 of r == 0
#pragma unroll
        for (int nt = 0; nt < 8; nt++) {
            const int c = colBase + warpN * 64 + nt * 8 + tig * 2;
            float v00 = acc[mt][nt][0] * scale, v01 = acc[mt][nt][1] * scale;
            float v10 = acc[mt][nt][2] * scale, v11 = acc[mt][nt][3] * scale;
            if (bias) { v00 += bias[c]; v01 += bias[c + 1]; v10 += bias[c]; v11 += bias[c + 1]; }
            if (EPI == 0) {
                float* C = (float*)OH + (long long)z * sOz;
                float2 o0 = {v00, v01}, o1 = {v10, v11};
                *(float2*)(C + (size_t)r * ldn + c) = o0;
                *(float2*)(C + (size_t)(r + 8) * ldn + c) = o1;
            } else if (EPI == 1) {
                const int kp = (c & 15) >> 1;
                const int lfr = ((r & 7) << 2) | (kp & 3);
                const int rg0 = (kp >> 2) << 1;
                const size_t tb = ((size_t)(r >> 4) * ldn + (c >> 4)) * 128 + lfr * 4 + rg0;
                uint32_t h0, l0, h1, l1;
                f16_split2(v00, v01, h0, l0);
                f16_split2(v10, v11, h1, l1);
                uint2 uh = {h0, h1}, ul = {l0, l1};
                *(uint2*)(OH + tb) = uh;
                *(uint2*)(OL + tb) = ul;
            } else if (EPI == 2) {
                const int kp = (c & 15) >> 1;
                const int lfr = ((r & 7) << 2) | (kp & 3);
                const int rg = kp >> 2;
                const size_t tb0 = ((size_t)(r >> 3) * ldn + (c >> 4)) * 64 + lfr * 2 + rg;
                const size_t tb1 = ((size_t)((r + 8) >> 3) * ldn + (c >> 4)) * 64 + lfr * 2 + rg;
                uint32_t h0, l0, h1, l1;
                f16_split2(v00, v01, h0, l0);
                f16_split2(v10, v11, h1, l1);
                OH[tb0] = h0; OH[tb1] = h1;
                OL[tb0] = l0; OL[tb1] = l1;
            } else {
                OH[(size_t)r * ldn + (c >> 1)] = f16_pack2(v00, v01);
                OH[(size_t)(r + 8) * ldn + (c >> 1)] = f16_pack2(v10, v11);
            }
        }
    }
}

// ============ pre-split: fp32 row-major [R x MODEL] -> A-frag planes =======
__global__ void split_a(const float* __restrict__ X, uint32_t* __restrict__ AH,
                        uint32_t* __restrict__ AL) {
    const size_t idx = (size_t)blockIdx.x * 256 + threadIdx.x;   // R*MODEL/8
    const int r = (int)(idx >> 7);
    const int o = (int)(idx & 127);
    const float4 v0 = ((const float4*)X)[idx * 2];
    const float4 v1 = ((const float4*)X)[idx * 2 + 1];
    const float f[8] = {v0.x, v0.y, v0.z, v0.w, v1.x, v1.y, v1.z, v1.w};
    const size_t tbase = ((size_t)(r >> 4) * (MODEL / 16) + (o >> 1)) * 128;
    const int regr = (r >> 3) & 1;
#pragma unroll
    for (int j = 0; j < 4; j++) {
        const int kp = (o & 1) * 4 + j;
        const int w = (((r & 7) << 2) | (kp & 3)) * 4 + (regr | ((kp >> 2) << 1));
        if (AL) {
            uint32_t hi, lo;
            f16_split2(f[2 * j], f[2 * j + 1], hi, lo);
            AH[tbase + w] = hi;
            AL[tbase + w] = lo;
        } else {
            AH[tbase + w] = f16_pack2(f[2 * j], f[2 * j + 1]);
        }
    }
}

// ===== pre-split: fp32 [MODEL x MODEL] W -> B-frag planes of W^T ===========
__global__ void split_bT(const float* __restrict__ W, uint32_t* __restrict__ BH,
                         uint32_t* __restrict__ BL) {
    __shared__ float s[64][65];
    const int k0 = blockIdx.y * 64, n0 = blockIdx.x * 64;
#pragma unroll
    for (int i = 0; i < 16; i++) {
        const int e = threadIdx.x + i * 256;
        s[e >> 6][e & 63] = W[(size_t)(k0 + (e >> 6)) * MODEL + n0 + (e & 63)];
    }
    __syncthreads();
#pragma unroll
    for (int i = 0; i < 8; i++) {
        const int e = threadIdx.x + i * 256;     // 0..2047
        const int n = e >> 5, kp = e & 31;
        const float a = s[kp * 2][n], b = s[kp * 2 + 1][n];
        const int nG = n0 + n;
        const int kp7 = kp & 7;
        const size_t w = ((size_t)(nG >> 3) * (MODEL / 16) + (k0 >> 4) + (kp >> 3)) * 64
                         + (((nG & 7) << 2) | (kp7 & 3)) * 2 + (kp7 >> 2);
        if (BL) {
            uint32_t hi, lo;
            f16_split2(a, b, hi, lo);
            BH[w] = hi;
            BL[w] = lo;
        } else {
            BH[w] = f16_pack2(a, b);
        }
    }
}

// ================ softmax: fp32 S row -> fp16 A-frag P plane ===============
__global__ void softmax_p(const float* __restrict__ S, uint32_t* __restrict__ P) {
    const int s = blockIdx.x;
    const float* row = S + (size_t)s * SEQ;
    const int tid = threadIdx.x;
    __shared__ float red[8];

    float x[8];
#pragma unroll
    for (int j = 0; j < 4; j++) {
        float2 v = *(const float2*)(row + 2 * (tid + j * 256));
        x[2 * j] = v.x;
        x[2 * j + 1] = v.y;
    }
    float m = x[0];
#pragma unroll
    for (int i = 1; i < 8; i++) m = fmaxf(m, x[i]);
#pragma unroll
    for (int o = 16; o > 0; o >>= 1) m = fmaxf(m, __shfl_xor_sync(0xffffffffu, m, o));
    if ((tid & 31) == 0) red[tid >> 5] = m;
    __syncthreads();
    m = red[0];
#pragma unroll
    for (int i = 1; i < 8; i++) m = fmaxf(m, red[i]);
    __syncthreads();

    float e[8], ssum = 0.0f;
#pragma unroll
    for (int i = 0; i < 8; i++) { e[i] = expf(x[i] - m); ssum += e[i]; }
#pragma unroll
    for (int o = 16; o > 0; o >>= 1) ssum += __shfl_xor_sync(0xffffffffu, ssum, o);
    if ((tid & 31) == 0) red[tid >> 5] = ssum;
    __syncthreads();
    ssum = 0.0f;
#pragma unroll
    for (int i = 0; i < 8; i++) ssum += red[i];
    const float inv = 1.0f / ssum;

    const int laneRow = (s & 7) << 2;
    const int regRow = (s >> 3) & 1;
    const size_t mtOff = (size_t)(s >> 4) * 128;
#pragma unroll
    for (int j = 0; j < 4; j++) {
        const int cp = tid + j * 256;
        const int pl = cp & 7, kt = cp >> 3;
        const int lfr = laneRow | (pl & 3);
        const int rg = regRow | ((pl >> 2) << 1);
        P[(mtOff + kt) * 128 + lfr * 4 + rg] = f16_pack2(e[2 * j] * inv, e[2 * j + 1] * inv);
    }
}

// ============ V half plane (row-major) -> VT B-frag tiles ==================
__global__ void vt_frag(const uint32_t* __restrict__ Vh, uint32_t* __restrict__ VT) {
    __shared__ uint32_t smv[64][36];            // stride 36: uint4 16B-aligned
    const int z = blockIdx.z;
    const int t0 = blockIdx.y * 64, d0 = blockIdx.x * 64;
    const int tr = threadIdx.x >> 3, dq = threadIdx.x & 7;
#pragma unroll
    for (int i = 0; i < 2; i++) {
        const int t = tr + i * 32;
        *(uint4*)&smv[t][dq * 4] =
            *(const uint4*)(Vh + (size_t)(z * SEQ + t0 + t) * (MODEL / 2) + (d0 >> 1) + dq * 4);
    }
    __syncthreads();
#pragma unroll
    for (int i = 0; i < 8; i++) {
        const int idx = threadIdx.x + i * 256;
        const int tile = idx >> 6, within = idx & 63;
        const int lfr = within >> 1, rg = within & 1;
        const int ntl = tile >> 2, ktl = tile & 3;
        const int n = ntl * 8 + (lfr >> 2);
        const int p = (lfr & 3) | (rg << 2);
        const int k = ktl * 16 + p * 2;
        const uint32_t a = smv[k][n >> 1], b = smv[k + 1][n >> 1];
        const uint32_t h0 = (n & 1) ? (a >> 16) : (a & 0xffffu);
        const uint32_t h1 = (n & 1) ? (b >> 16) : (b & 0xffffu);
        VT[((size_t)(z * 128 + (d0 >> 3) + ntl) * 128 + (t0 >> 4) + ktl) * 64 + within] =
            h0 | (h1 << 16);
    }
}

// ------------------------------- launcher ----------------------------------
extern "C" void kernel_launch(void* const* d_in, const int* in_sizes, int n_in,
                              void* d_out, int out_size) {
    const float* q  = (const float*)d_in[0];
    const float* k  = (const float*)d_in[1];
    const float* v  = (const float*)d_in[2];
    const float* Wq = (const float*)d_in[3];
    const float* Wk = (const float*)d_in[4];
    const float* Wv = (const float*)d_in[5];
    const float* bq = (const float*)d_in[6];
    const float* bk = (const float*)d_in[7];
    const float* bv = (const float*)d_in[8];
    float* out = (float*)d_out;

    uint32_t *qAH, *qAL, *kAH, *kAL, *vAH;
    uint32_t *WqH, *WqL, *WkH, *WkL, *WvH;
    uint32_t *QH, *QL, *KH, *KL, *Vh, *VT, *P;
    float* Sp;
    cudaGetSymbolAddress((void**)&qAH, g_qAH);
    cudaGetSymbolAddress((void**)&qAL, g_qAL);
    cudaGetSymbolAddress((void**)&kAH, g_kAH);
    cudaGetSymbolAddress((void**)&kAL, g_kAL);
    cudaGetSymbolAddress((void**)&vAH, g_vAH);
    cudaGetSymbolAddress((void**)&WqH, g_WqH);
    cudaGetSymbolAddress((void**)&WqL, g_WqL);
    cudaGetSymbolAddress((void**)&WkH, g_WkH);
    cudaGetSymbolAddress((void**)&WkL, g_WkL);
    cudaGetSymbolAddress((void**)&WvH, g_WvH);
    cudaGetSymbolAddress((void**)&QH, g_QH);
    cudaGetSymbolAddress((void**)&QL, g_QL);
    cudaGetSymbolAddress((void**)&KH, g_KH);
    cudaGetSymbolAddress((void**)&KL, g_KL);
    cudaGetSymbolAddress((void**)&Vh, g_Vh);
    cudaGetSymbolAddress((void**)&VT, g_VT);
    cudaGetSymbolAddress((void**)&P,  g_P);
    cudaGetSymbolAddress((void**)&Sp, g_S);

    // ---- pre-split inputs into fragment planes ----
    const int nsplit = (int)((size_t)MTOT * MODEL / 8 / 256);   // 4096
    split_a<<<nsplit, 256>>>(q, qAH, qAL);
    split_a<<<nsplit, 256>>>(k, kAH, kAL);
    split_a<<<nsplit, 256>>>(v, vAH, nullptr);
    const dim3 gw(16, 16);
    split_bT<<<gw, 256>>>(Wq, WqH, WqL);
    split_bT<<<gw, 256>>>(Wk, WkH, WkL);
    split_bT<<<gw, 256>>>(Wv, WvH, nullptr);

    // ---- projections ----
    const dim3 gproj(MODEL / 128, MTOT / 128, 1);   // (8, 64)
    gemm_c<3, 1><<<gproj, 128, 32768>>>(qAH, qAL, 64, WqH, WqL, 64,
                                        QH, QL, MODEL / 16, bq, 1.0f, 64, 0, 0, 0);
    gemm_c<3, 2><<<gproj, 128, 32768>>>(kAH, kAL, 64, WkH, WkL, 64,
                                        KH, KL, MODEL / 16, bk, 1.0f, 64, 0, 0, 0);
    gemm_c<1, 3><<<gproj, 128, 16384>>>(vAH, nullptr, 64, WvH, nullptr, 64,
                                        Vh, nullptr, MODEL / 2, bv, 1.0f, 64, 0, 0, 0);

    // ---- scores: S = (Q K^T) / 32 ----
    const dim3 gsc(SEQ / 128, SEQ / 128, BATCH);    // (16, 16, 4)
    gemm_c<3, 0><<<gsc, 128, 32768>>>(QH, QL, 64, KH, KL, 64,
                                      (uint32_t*)Sp, nullptr, SEQ, nullptr, 0.03125f, 64,
                                      128, 256, (long long)SEQ * SEQ);

    // ---- softmax -> P plane; V -> VT tiles ----
    softmax_p<<<MTOT, 256>>>(Sp, P);
    vt_frag<<<dim3(MODEL / 64, SEQ / 64, BATCH), 256>>>(Vh, VT);

    // ---- O = P V ----
    const dim3 gpv(MODEL / 128, SEQ / 128, BATCH);  // (8, 16, 4)
    gemm_c<1, 0><<<gpv, 128, 16384>>>(P, nullptr, SEQ / 16, VT, nullptr, SEQ / 16,
                                      (uint32_t*)out, nullptr, MODEL, nullptr, 1.0f, SEQ / 16,
                                      128, 128, (long long)SEQ * MODEL);
}

// round 10
// speedup vs baseline: 4.1113x; 1.0401x over previous
#include <cuda_runtime.h>
#include <cuda_fp16.h>
#include <cstdint>
#include <math.h>

// ---------------------------------------------------------------------------
// DotProductAttention (sm_103 plain -> mma.sync m16n8k16 fp16).
// R10: 3-stage cp.async ring with ONE __syncthreads per k-iter (was 2),
// prefetch depth 2. Everything else identical to R9.
// ---------------------------------------------------------------------------

#define BATCH 4
#define SEQ   2048
#define MODEL 1024
#define MTOT  (BATCH * SEQ)   // 8192

// pre-split input planes
__device__ uint32_t g_qAH[(size_t)MTOT * MODEL / 2];
__device__ uint32_t g_qAL[(size_t)MTOT * MODEL / 2];
__device__ uint32_t g_kAH[(size_t)MTOT * MODEL / 2];
__device__ uint32_t g_kAL[(size_t)MTOT * MODEL / 2];
__device__ uint32_t g_vAH[(size_t)MTOT * MODEL / 2];
__device__ uint32_t g_WqH[MODEL * MODEL / 2];
__device__ uint32_t g_WqL[MODEL * MODEL / 2];
__device__ uint32_t g_WkH[MODEL * MODEL / 2];
__device__ uint32_t g_WkL[MODEL * MODEL / 2];
__device__ uint32_t g_WvH[MODEL * MODEL / 2];
// projected planes
__device__ uint32_t g_QH[(size_t)MTOT * MODEL / 2];
__device__ uint32_t g_QL[(size_t)MTOT * MODEL / 2];
__device__ uint32_t g_KH[(size_t)MTOT * MODEL / 2];
__device__ uint32_t g_KL[(size_t)MTOT * MODEL / 2];
__device__ uint32_t g_Vh[(size_t)MTOT * MODEL / 2];   // row-major half2
__device__ uint32_t g_VT[(size_t)BATCH * (MODEL / 8) * (SEQ / 16) * 64];
__device__ uint32_t g_P [(size_t)MTOT * (SEQ / 2)];
__device__ float    g_S [(size_t)BATCH * SEQ * SEQ];

__device__ __forceinline__ void f16_split2(float a, float b, uint32_t& hi, uint32_t& lo) {
    __half ha = __float2half_rn(a), hb = __float2half_rn(b);
    __half la = __float2half_rn(a - __half2float(ha));
    __half lb = __float2half_rn(b - __half2float(hb));
    hi = ((uint32_t)__half_as_ushort(hb) << 16) | (uint32_t)__half_as_ushort(ha);
    lo = ((uint32_t)__half_as_ushort(lb) << 16) | (uint32_t)__half_as_ushort(la);
}
__device__ __forceinline__ uint32_t f16_pack2(float a, float b) {
    __half ha = __float2half_rn(a), hb = __float2half_rn(b);
    return ((uint32_t)__half_as_ushort(hb) << 16) | (uint32_t)__half_as_ushort(ha);
}
__device__ __forceinline__ void mma_f16(float* c, const uint32_t* a, const uint32_t* b) {
    asm volatile(
        "mma.sync.aligned.m16n8k16.row.col.f32.f16.f16.f32 "
        "{%0,%1,%2,%3}, {%4,%5,%6,%7}, {%8,%9}, {%0,%1,%2,%3};"
        : "+f"(c[0]), "+f"(c[1]), "+f"(c[2]), "+f"(c[3])
        : "r"(a[0]), "r"(a[1]), "r"(a[2]), "r"(a[3]), "r"(b[0]), "r"(b[1]));
}
__device__ __forceinline__ void cp16(uint32_t s, const void* g) {
    asm volatile("cp.async.cg.shared.global [%0], [%1], 16;" :: "r"(s), "l"(g));
}
__device__ __forceinline__ void cp_commit() { asm volatile("cp.async.commit_group;" ::: "memory"); }
template <int N> __device__ __forceinline__ void cp_wait() {
    asm volatile("cp.async.wait_group %0;" :: "n"(N) : "memory");
}

// ================= unified plane-in GEMM, warp tile 64x64 ==================
// EPI: 0 = fp32 C, 1 = A-frag hi/lo planes, 2 = B-frag hi/lo planes,
//      3 = half2 row-major plane
template <int PASSES, int EPI>
__global__ void __launch_bounds__(128, 2) gemm_c(
    const uint32_t* __restrict__ AH, const uint32_t* __restrict__ AL, int nktA,
    const uint32_t* __restrict__ BH, const uint32_t* __restrict__ BL, int nktB,
    uint32_t* __restrict__ OH, uint32_t* __restrict__ OL, int ldn,
    const float* __restrict__ bias, float scale, int nk,
    int mtZ, int ntZ, long long sOz)
{
    constexpr bool P3 = (PASSES == 3);
    constexpr int STG = P3 ? 4096 : 2048;       // u32 per stage
    constexpr int OFF_AL = 1024;
    constexpr int OFF_BHs = P3 ? 2048 : 1024;
    constexpr int OFF_BLs = OFF_BHs + 1024;

    extern __shared__ uint32_t sm[];
    const uint32_t sb0 = (uint32_t)__cvta_generic_to_shared(sm);
    const int tid = threadIdx.x, wid = tid >> 5, lane = tid & 31;
    const int warpM = wid & 1, warpN = wid >> 1;
    const int z = blockIdx.z;
    const int mtBase = z * mtZ + blockIdx.y * 8;
    const int ntBase = z * ntZ + blockIdx.x * 16;
    const int rowBase = blockIdx.y * 128, colBase = blockIdx.x * 128;

    int aT[2], aW[2], bT[2], bW[2];
    const uint32_t *gA[2], *gAl[2], *gB[2], *gBl[2];
#pragma unroll
    for (int g = 0; g < 2; g++) {
        const int ga = tid * 2 + g;
        aT[g] = ga >> 5; aW[g] = (ga & 31) * 4;
        bT[g] = ga >> 4; bW[g] = (ga & 15) * 4;
        gA[g] = AH + (size_t)(mtBase + aT[g]) * nktA * 128 + aW[g];
        gB[g] = BH + (size_t)(ntBase + bT[g]) * nktB * 64 + bW[g];
        if (P3) {
            gAl[g] = AL + (size_t)(mtBase + aT[g]) * nktA * 128 + aW[g];
            gBl[g] = BL + (size_t)(ntBase + bT[g]) * nktB * 64 + bW[g];
        }
    }

    auto issue = [&](int kt, int stg) {
        const uint32_t s = sb0 + stg * (STG * 4);
#pragma unroll
        for (int g = 0; g < 2; g++) {
            cp16(s + (aT[g] * 128 + aW[g]) * 4, gA[g] + (size_t)kt * 128);
            if (P3) cp16(s + (OFF_AL + aT[g] * 128 + aW[g]) * 4, gAl[g] + (size_t)kt * 128);
            cp16(s + (OFF_BHs + bT[g] * 64 + bW[g]) * 4, gB[g] + (size_t)kt * 64);
            if (P3) cp16(s + (OFF_BLs + bT[g] * 64 + bW[g]) * 4, gBl[g] + (size_t)kt * 64);
        }
        cp_commit();
    };

    float acc[4][8][4];
#pragma unroll
    for (int mt = 0; mt < 4; mt++)
#pragma unroll
        for (int nt = 0; nt < 8; nt++)
#pragma unroll
            for (int e = 0; e < 4; e++) acc[mt][nt][e] = 0.0f;

    // 3-stage ring, prefetch depth 2
    issue(0, 0);
    issue(1, 1);

    int slot = 0;                               // slot of stage i (i % 3)
    for (int i = 0; i < nk; i++) {
        if (i + 1 < nk) cp_wait<1>();           // stage i landed (newest may fly)
        else            cp_wait<0>();           // final stage must be complete
        __syncthreads();                        // publish stage i; stage i-1 reads done

        if (i + 2 < nk) {
            int nslot = slot + 2;
            if (nslot >= 3) nslot -= 3;
            issue(i + 2, nslot);                // reuses slot of stage i-1: safe
        }

        const uint32_t* s = sm + slot * STG;
        uint32_t aHi[4][4], aLo[4][4];
#pragma unroll
        for (int mt = 0; mt < 4; mt++) {
            const uint32_t* ap = s + (warpM * 4 + mt) * 128 + lane * 4;
            *(uint4*)aHi[mt] = *(const uint4*)ap;
            if (P3) *(uint4*)aLo[mt] = *(const uint4*)(ap + OFF_AL);
        }
#pragma unroll
        for (int h = 0; h < 2; h++) {
            uint32_t bHi[4][2], bLo[4][2];
#pragma unroll
            for (int n4 = 0; n4 < 4; n4++) {
                const uint32_t* bp = s + OFF_BHs + (warpN * 8 + h * 4 + n4) * 64 + lane * 2;
                *(uint2*)bHi[n4] = *(const uint2*)bp;
                if (P3) *(uint2*)bLo[n4] = *(const uint2*)(bp + 1024);
            }
#pragma unroll
            for (int mt = 0; mt < 4; mt++)
#pragma unroll
                for (int n4 = 0; n4 < 4; n4++) {
                    float* c = acc[mt][h * 4 + n4];
                    mma_f16(c, aHi[mt], bHi[n4]);
                    if (P3) { mma_f16(c, aHi[mt], bLo[n4]); mma_f16(c, aLo[mt], bHi[n4]); }
                }
        }

        if (++slot == 3) slot = 0;
    }

    // ---- epilogue ----
    const int gID = lane >> 2, tig = lane & 3;
#pragma unroll
    for (int mt = 0; mt < 4; mt++) {
        const int r = rowBase + warpM * 64 + mt * 16 + gID;    // bit3 of r == 0
#pragma unroll
        for (int nt = 0; nt < 8; nt++) {
            const int c = colBase + warpN * 64 + nt * 8 + tig * 2;
            float v00 = acc[mt][nt][0] * scale, v01 = acc[mt][nt][1] * scale;
            float v10 = acc[mt][nt][2] * scale, v11 = acc[mt][nt][3] * scale;
            if (bias) { v00 += bias[c]; v01 += bias[c + 1]; v10 += bias[c]; v11 += bias[c + 1]; }
            if (EPI == 0) {
                float* C = (float*)OH + (long long)z * sOz;
                float2 o0 = {v00, v01}, o1 = {v10, v11};
                *(float2*)(C + (size_t)r * ldn + c) = o0;
                *(float2*)(C + (size_t)(r + 8) * ldn + c) = o1;
            } else if (EPI == 1) {
                const int kp = (c & 15) >> 1;
                const int lfr = ((r & 7) << 2) | (kp & 3);
                const int rg0 = (kp >> 2) << 1;
                const size_t tb = ((size_t)(r >> 4) * ldn + (c >> 4)) * 128 + lfr * 4 + rg0;
                uint32_t h0, l0, h1, l1;
                f16_split2(v00, v01, h0, l0);
                f16_split2(v10, v11, h1, l1);
                uint2 uh = {h0, h1}, ul = {l0, l1};
                *(uint2*)(OH + tb) = uh;
                *(uint2*)(OL + tb) = ul;
            } else if (EPI == 2) {
                const int kp = (c & 15) >> 1;
                const int lfr = ((r & 7) << 2) | (kp & 3);
                const int rg = kp >> 2;
                const size_t tb0 = ((size_t)(r >> 3) * ldn + (c >> 4)) * 64 + lfr * 2 + rg;
                const size_t tb1 = ((size_t)((r + 8) >> 3) * ldn + (c >> 4)) * 64 + lfr * 2 + rg;
                uint32_t h0, l0, h1, l1;
                f16_split2(v00, v01, h0, l0);
                f16_split2(v10, v11, h1, l1);
                OH[tb0] = h0; OH[tb1] = h1;
                OL[tb0] = l0; OL[tb1] = l1;
            } else {
                OH[(size_t)r * ldn + (c >> 1)] = f16_pack2(v00, v01);
                OH[(size_t)(r + 8) * ldn + (c >> 1)] = f16_pack2(v10, v11);
            }
        }
    }
}

// ============ pre-split: fp32 row-major [R x MODEL] -> A-frag planes =======
__global__ void split_a(const float* __restrict__ X, uint32_t* __restrict__ AH,
                        uint32_t* __restrict__ AL) {
    const size_t idx = (size_t)blockIdx.x * 256 + threadIdx.x;   // R*MODEL/8
    const int r = (int)(idx >> 7);
    const int o = (int)(idx & 127);
    const float4 v0 = ((const float4*)X)[idx * 2];
    const float4 v1 = ((const float4*)X)[idx * 2 + 1];
    const float f[8] = {v0.x, v0.y, v0.z, v0.w, v1.x, v1.y, v1.z, v1.w};
    const size_t tbase = ((size_t)(r >> 4) * (MODEL / 16) + (o >> 1)) * 128;
    const int regr = (r >> 3) & 1;
#pragma unroll
    for (int j = 0; j < 4; j++) {
        const int kp = (o & 1) * 4 + j;
        const int w = (((r & 7) << 2) | (kp & 3)) * 4 + (regr | ((kp >> 2) << 1));
        if (AL) {
            uint32_t hi, lo;
            f16_split2(f[2 * j], f[2 * j + 1], hi, lo);
            AH[tbase + w] = hi;
            AL[tbase + w] = lo;
        } else {
            AH[tbase + w] = f16_pack2(f[2 * j], f[2 * j + 1]);
        }
    }
}

// ===== pre-split: fp32 [MODEL x MODEL] W -> B-frag planes of W^T ===========
__global__ void split_bT(const float* __restrict__ W, uint32_t* __restrict__ BH,
                         uint32_t* __restrict__ BL) {
    __shared__ float s[64][65];
    const int k0 = blockIdx.y * 64, n0 = blockIdx.x * 64;
#pragma unroll
    for (int i = 0; i < 16; i++) {
        const int e = threadIdx.x + i * 256;
        s[e >> 6][e & 63] = W[(size_t)(k0 + (e >> 6)) * MODEL + n0 + (e & 63)];
    }
    __syncthreads();
#pragma unroll
    for (int i = 0; i < 8; i++) {
        const int e = threadIdx.x + i * 256;     // 0..2047
        const int n = e >> 5, kp = e & 31;
        const float a = s[kp * 2][n], b = s[kp * 2 + 1][n];
        const int nG = n0 + n;
        const int kp7 = kp & 7;
        const size_t w = ((size_t)(nG >> 3) * (MODEL / 16) + (k0 >> 4) + (kp >> 3)) * 64
                         + (((nG & 7) << 2) | (kp7 & 3)) * 2 + (kp7 >> 2);
        if (BL) {
            uint32_t hi, lo;
            f16_split2(a, b, hi, lo);
            BH[w] = hi;
            BL[w] = lo;
        } else {
            BH[w] = f16_pack2(a, b);
        }
    }
}

// ================ softmax: fp32 S row -> fp16 A-frag P plane ===============
__global__ void softmax_p(const float* __restrict__ S, uint32_t* __restrict__ P) {
    const int s = blockIdx.x;
    const float* row = S + (size_t)s * SEQ;
    const int tid = threadIdx.x;
    __shared__ float red[8];

    float x[8];
#pragma unroll
    for (int j = 0; j < 4; j++) {
        float2 v = *(const float2*)(row + 2 * (tid + j * 256));
        x[2 * j] = v.x;
        x[2 * j + 1] = v.y;
    }
    float m = x[0];
#pragma unroll
    for (int i = 1; i < 8; i++) m = fmaxf(m, x[i]);
#pragma unroll
    for (int o = 16; o > 0; o >>= 1) m = fmaxf(m, __shfl_xor_sync(0xffffffffu, m, o));
    if ((tid & 31) == 0) red[tid >> 5] = m;
    __syncthreads();
    m = red[0];
#pragma unroll
    for (int i = 1; i < 8; i++) m = fmaxf(m, red[i]);
    __syncthreads();

    float e[8], ssum = 0.0f;
#pragma unroll
    for (int i = 0; i < 8; i++) { e[i] = expf(x[i] - m); ssum += e[i]; }
#pragma unroll
    for (int o = 16; o > 0; o >>= 1) ssum += __shfl_xor_sync(0xffffffffu, ssum, o);
    if ((tid & 31) == 0) red[tid >> 5] = ssum;
    __syncthreads();
    ssum = 0.0f;
#pragma unroll
    for (int i = 0; i < 8; i++) ssum += red[i];
    const float inv = 1.0f / ssum;

    const int laneRow = (s & 7) << 2;
    const int regRow = (s >> 3) & 1;
    const size_t mtOff = (size_t)(s >> 4) * 128;
#pragma unroll
    for (int j = 0; j < 4; j++) {
        const int cp = tid + j * 256;
        const int pl = cp & 7, kt = cp >> 3;
        const int lfr = laneRow | (pl & 3);
        const int rg = regRow | ((pl >> 2) << 1);
        P[(mtOff + kt) * 128 + lfr * 4 + rg] = f16_pack2(e[2 * j] * inv, e[2 * j + 1] * inv);
    }
}

// ============ V half plane (row-major) -> VT B-frag tiles ==================
__global__ void vt_frag(const uint32_t* __restrict__ Vh, uint32_t* __restrict__ VT) {
    __shared__ uint32_t smv[64][36];            // stride 36: uint4 16B-aligned
    const int z = blockIdx.z;
    const int t0 = blockIdx.y * 64, d0 = blockIdx.x * 64;
    const int tr = threadIdx.x >> 3, dq = threadIdx.x & 7;
#pragma unroll
    for (int i = 0; i < 2; i++) {
        const int t = tr + i * 32;
        *(uint4*)&smv[t][dq * 4] =
            *(const uint4*)(Vh + (size_t)(z * SEQ + t0 + t) * (MODEL / 2) + (d0 >> 1) + dq * 4);
    }
    __syncthreads();
#pragma unroll
    for (int i = 0; i < 8; i++) {
        const int idx = threadIdx.x + i * 256;
        const int tile = idx >> 6, within = idx & 63;
        const int lfr = within >> 1, rg = within & 1;
        const int ntl = tile >> 2, ktl = tile & 3;
        const int n = ntl * 8 + (lfr >> 2);
        const int p = (lfr & 3) | (rg << 2);
        const int k = ktl * 16 + p * 2;
        const uint32_t a = smv[k][n >> 1], b = smv[k + 1][n >> 1];
        const uint32_t h0 = (n & 1) ? (a >> 16) : (a & 0xffffu);
        const uint32_t h1 = (n & 1) ? (b >> 16) : (b & 0xffffu);
        VT[((size_t)(z * 128 + (d0 >> 3) + ntl) * 128 + (t0 >> 4) + ktl) * 64 + within] =
            h0 | (h1 << 16);
    }
}

// ------------------------------- launcher ----------------------------------
extern "C" void kernel_launch(void* const* d_in, const int* in_sizes, int n_in,
                              void* d_out, int out_size) {
    const float* q  = (const float*)d_in[0];
    const float* k  = (const float*)d_in[1];
    const float* v  = (const float*)d_in[2];
    const float* Wq = (const float*)d_in[3];
    const float* Wk = (const float*)d_in[4];
    const float* Wv = (const float*)d_in[5];
    const float* bq = (const float*)d_in[6];
    const float* bk = (const float*)d_in[7];
    const float* bv = (const float*)d_in[8];
    float* out = (float*)d_out;

    uint32_t *qAH, *qAL, *kAH, *kAL, *vAH;
    uint32_t *WqH, *WqL, *WkH, *WkL, *WvH;
    uint32_t *QH, *QL, *KH, *KL, *Vh, *VT, *P;
    float* Sp;
    cudaGetSymbolAddress((void**)&qAH, g_qAH);
    cudaGetSymbolAddress((void**)&qAL, g_qAL);
    cudaGetSymbolAddress((void**)&kAH, g_kAH);
    cudaGetSymbolAddress((void**)&kAL, g_kAL);
    cudaGetSymbolAddress((void**)&vAH, g_vAH);
    cudaGetSymbolAddress((void**)&WqH, g_WqH);
    cudaGetSymbolAddress((void**)&WqL, g_WqL);
    cudaGetSymbolAddress((void**)&WkH, g_WkH);
    cudaGetSymbolAddress((void**)&WkL, g_WkL);
    cudaGetSymbolAddress((void**)&WvH, g_WvH);
    cudaGetSymbolAddress((void**)&QH, g_QH);
    cudaGetSymbolAddress((void**)&QL, g_QL);
    cudaGetSymbolAddress((void**)&KH, g_KH);
    cudaGetSymbolAddress((void**)&KL, g_KL);
    cudaGetSymbolAddress((void**)&Vh, g_Vh);
    cudaGetSymbolAddress((void**)&VT, g_VT);
    cudaGetSymbolAddress((void**)&P,  g_P);
    cudaGetSymbolAddress((void**)&Sp, g_S);

    // ---- pre-split inputs into fragment planes ----
    const int nsplit = (int)((size_t)MTOT * MODEL / 8 / 256);   // 4096
    split_a<<<nsplit, 256>>>(q, qAH, qAL);
    split_a<<<nsplit, 256>>>(k, kAH, kAL);
    split_a<<<nsplit, 256>>>(v, vAH, nullptr);
    const dim3 gw(16, 16);
    split_bT<<<gw, 256>>>(Wq, WqH, WqL);
    split_bT<<<gw, 256>>>(Wk, WkH, WkL);
    split_bT<<<gw, 256>>>(Wv, WvH, nullptr);

    // ---- projections ----
    const dim3 gproj(MODEL / 128, MTOT / 128, 1);   // (8, 64)
    gemm_c<3, 1><<<gproj, 128, 49152>>>(qAH, qAL, 64, WqH, WqL, 64,
                                        QH, QL, MODEL / 16, bq, 1.0f, 64, 0, 0, 0);
    gemm_c<3, 2><<<gproj, 128, 49152>>>(kAH, kAL, 64, WkH, WkL, 64,
                                        KH, KL, MODEL / 16, bk, 1.0f, 64, 0, 0, 0);
    gemm_c<1, 3><<<gproj, 128, 24576>>>(vAH, nullptr, 64, WvH, nullptr, 64,
                                        Vh, nullptr, MODEL / 2, bv, 1.0f, 64, 0, 0, 0);

    // ---- scores: S = (Q K^T) / 32 ----
    const dim3 gsc(SEQ / 128, SEQ / 128, BATCH);    // (16, 16, 4)
    gemm_c<3, 0><<<gsc, 128, 49152>>>(QH, QL, 64, KH, KL, 64,
                                      (uint32_t*)Sp, nullptr, SEQ, nullptr, 0.03125f, 64,
                                      128, 256, (long long)SEQ * SEQ);

    // ---- softmax -> P plane; V -> VT tiles ----
    softmax_p<<<MTOT, 256>>>(Sp, P);
    vt_frag<<<dim3(MODEL / 64, SEQ / 64, BATCH), 256>>>(Vh, VT);

    // ---- O = P V ----
    const dim3 gpv(MODEL / 128, SEQ / 128, BATCH);  // (8, 16, 4)
    gemm_c<1, 0><<<gpv, 128, 24576>>>(P, nullptr, SEQ / 16, VT, nullptr, SEQ / 16,
                                      (uint32_t*)out, nullptr, MODEL, nullptr, 1.0f, SEQ / 16,
                                      128, 128, (long long)SEQ * MODEL);
}

// round 11
// speedup vs baseline: 4.5098x; 1.0969x over previous
#include <cuda_runtime.h>
#include <cuda_fp16.h>
#include <cstdint>
#include <math.h>

// ---------------------------------------------------------------------------
// DotProductAttention (sm_103 plain -> mma.sync m16n8k16 fp16).
// R11: merged Q+K projection launch, merged split launches, fused
// softmax+vt kernel, pass-outer mma ordering (acc reuse distance 3 -> 32).
// ---------------------------------------------------------------------------

#define BATCH 4
#define SEQ   2048
#define MODEL 1024
#define MTOT  (BATCH * SEQ)   // 8192

__device__ uint32_t g_qAH[(size_t)MTOT * MODEL / 2];
__device__ uint32_t g_qAL[(size_t)MTOT * MODEL / 2];
__device__ uint32_t g_kAH[(size_t)MTOT * MODEL / 2];
__device__ uint32_t g_kAL[(size_t)MTOT * MODEL / 2];
__device__ uint32_t g_vAH[(size_t)MTOT * MODEL / 2];
__device__ uint32_t g_WqH[MODEL * MODEL / 2];
__device__ uint32_t g_WqL[MODEL * MODEL / 2];
__device__ uint32_t g_WkH[MODEL * MODEL / 2];
__device__ uint32_t g_WkL[MODEL * MODEL / 2];
__device__ uint32_t g_WvH[MODEL * MODEL / 2];
__device__ uint32_t g_QH[(size_t)MTOT * MODEL / 2];
__device__ uint32_t g_QL[(size_t)MTOT * MODEL / 2];
__device__ uint32_t g_KH[(size_t)MTOT * MODEL / 2];
__device__ uint32_t g_KL[(size_t)MTOT * MODEL / 2];
__device__ uint32_t g_Vh[(size_t)MTOT * MODEL / 2];
__device__ uint32_t g_VT[(size_t)BATCH * (MODEL / 8) * (SEQ / 16) * 64];
__device__ uint32_t g_P [(size_t)MTOT * (SEQ / 2)];
__device__ float    g_S [(size_t)BATCH * SEQ * SEQ];

__device__ __forceinline__ void f16_split2(float a, float b, uint32_t& hi, uint32_t& lo) {
    __half ha = __float2half_rn(a), hb = __float2half_rn(b);
    __half la = __float2half_rn(a - __half2float(ha));
    __half lb = __float2half_rn(b - __half2float(hb));
    hi = ((uint32_t)__half_as_ushort(hb) << 16) | (uint32_t)__half_as_ushort(ha);
    lo = ((uint32_t)__half_as_ushort(lb) << 16) | (uint32_t)__half_as_ushort(la);
}
__device__ __forceinline__ uint32_t f16_pack2(float a, float b) {
    __half ha = __float2half_rn(a), hb = __float2half_rn(b);
    return ((uint32_t)__half_as_ushort(hb) << 16) | (uint32_t)__half_as_ushort(ha);
}
__device__ __forceinline__ void mma_f16(float* c, const uint32_t* a, const uint32_t* b) {
    asm volatile(
        "mma.sync.aligned.m16n8k16.row.col.f32.f16.f16.f32 "
        "{%0,%1,%2,%3}, {%4,%5,%6,%7}, {%8,%9}, {%0,%1,%2,%3};"
        : "+f"(c[0]), "+f"(c[1]), "+f"(c[2]), "+f"(c[3])
        : "r"(a[0]), "r"(a[1]), "r"(a[2]), "r"(a[3]), "r"(b[0]), "r"(b[1]));
}
__device__ __forceinline__ void cp16(uint32_t s, const void* g) {
    asm volatile("cp.async.cg.shared.global [%0], [%1], 16;" :: "r"(s), "l"(g));
}
__device__ __forceinline__ void cp_commit() { asm volatile("cp.async.commit_group;" ::: "memory"); }
template <int N> __device__ __forceinline__ void cp_wait() {
    asm volatile("cp.async.wait_group %0;" :: "n"(N) : "memory");
}

// ===================== shared GEMM core (3-stage ring) =====================
template <int PASSES>
__device__ __forceinline__ void gemm_core(
    uint32_t* smBase, uint32_t sb0,
    const uint32_t* __restrict__ AH, const uint32_t* __restrict__ AL, int nktA,
    const uint32_t* __restrict__ BH, const uint32_t* __restrict__ BL, int nktB,
    int mtBase, int ntBase, int nk, float (&acc)[4][8][4])
{
    constexpr bool P3 = (PASSES == 3);
    constexpr int STG = P3 ? 4096 : 2048;
    constexpr int OFF_AL = 1024;
    constexpr int OFF_BHs = P3 ? 2048 : 1024;
    constexpr int OFF_BLs = OFF_BHs + 1024;

    const int tid = threadIdx.x, wid = tid >> 5, lane = tid & 31;
    const int warpM = wid & 1, warpN = wid >> 1;

    int aT[2], aW[2], bT[2], bW[2];
    const uint32_t *gA[2], *gAl[2], *gB[2], *gBl[2];
#pragma unroll
    for (int g = 0; g < 2; g++) {
        const int ga = tid * 2 + g;
        aT[g] = ga >> 5; aW[g] = (ga & 31) * 4;
        bT[g] = ga >> 4; bW[g] = (ga & 15) * 4;
        gA[g] = AH + (size_t)(mtBase + aT[g]) * nktA * 128 + aW[g];
        gB[g] = BH + (size_t)(ntBase + bT[g]) * nktB * 64 + bW[g];
        if (P3) {
            gAl[g] = AL + (size_t)(mtBase + aT[g]) * nktA * 128 + aW[g];
            gBl[g] = BL + (size_t)(ntBase + bT[g]) * nktB * 64 + bW[g];
        }
    }

    auto issue = [&](int kt, int stg) {
        const uint32_t s = sb0 + stg * (STG * 4);
#pragma unroll
        for (int g = 0; g < 2; g++) {
            cp16(s + (aT[g] * 128 + aW[g]) * 4, gA[g] + (size_t)kt * 128);
            if (P3) cp16(s + (OFF_AL + aT[g] * 128 + aW[g]) * 4, gAl[g] + (size_t)kt * 128);
            cp16(s + (OFF_BHs + bT[g] * 64 + bW[g]) * 4, gB[g] + (size_t)kt * 64);
            if (P3) cp16(s + (OFF_BLs + bT[g] * 64 + bW[g]) * 4, gBl[g] + (size_t)kt * 64);
        }
        cp_commit();
    };

#pragma unroll
    for (int mt = 0; mt < 4; mt++)
#pragma unroll
        for (int nt = 0; nt < 8; nt++)
#pragma unroll
            for (int e = 0; e < 4; e++) acc[mt][nt][e] = 0.0f;

    issue(0, 0);
    issue(1, 1);

    int slot = 0;
    for (int i = 0; i < nk; i++) {
        if (i + 1 < nk) cp_wait<1>();
        else            cp_wait<0>();
        __syncthreads();

        if (i + 2 < nk) {
            int nslot = slot + 2;
            if (nslot >= 3) nslot -= 3;
            issue(i + 2, nslot);
        }

        const uint32_t* s = smBase + slot * STG;
        uint32_t aHi[4][4], aLo[4][4], bHi[8][2], bLo[8][2];
#pragma unroll
        for (int mt = 0; mt < 4; mt++) {
            const uint32_t* ap = s + (warpM * 4 + mt) * 128 + lane * 4;
            *(uint4*)aHi[mt] = *(const uint4*)ap;
            if (P3) *(uint4*)aLo[mt] = *(const uint4*)(ap + OFF_AL);
        }
#pragma unroll
        for (int nt = 0; nt < 8; nt++) {
            const uint32_t* bp = s + OFF_BHs + (warpN * 8 + nt) * 64 + lane * 2;
            *(uint2*)bHi[nt] = *(const uint2*)bp;
            if (P3) *(uint2*)bLo[nt] = *(const uint2*)(bp + 1024);
        }
        // pass-outer: acc reuse distance = 32 independent mmas
#pragma unroll
        for (int mt = 0; mt < 4; mt++)
#pragma unroll
            for (int nt = 0; nt < 8; nt++)
                mma_f16(acc[mt][nt], aHi[mt], bHi[nt]);
        if (P3) {
#pragma unroll
            for (int mt = 0; mt < 4; mt++)
#pragma unroll
                for (int nt = 0; nt < 8; nt++)
                    mma_f16(acc[mt][nt], aHi[mt], bLo[nt]);
#pragma unroll
            for (int mt = 0; mt < 4; mt++)
#pragma unroll
                for (int nt = 0; nt < 8; nt++)
                    mma_f16(acc[mt][nt], aLo[mt], bHi[nt]);
        }

        if (++slot == 3) slot = 0;
    }
}

// ============== merged Q+K projection (grid.z selects operand set) =========
__global__ void __launch_bounds__(128, 2) gemm_qk(
    const uint32_t* __restrict__ qAH, const uint32_t* __restrict__ qAL,
    const uint32_t* __restrict__ WqH, const uint32_t* __restrict__ WqL,
    const float* __restrict__ bq,
    uint32_t* __restrict__ QH, uint32_t* __restrict__ QL,
    const uint32_t* __restrict__ kAH, const uint32_t* __restrict__ kAL,
    const uint32_t* __restrict__ WkH, const uint32_t* __restrict__ WkL,
    const float* __restrict__ bk,
    uint32_t* __restrict__ KH, uint32_t* __restrict__ KL)
{
    extern __shared__ uint32_t sm[];
    const uint32_t sb0 = (uint32_t)__cvta_generic_to_shared(sm);
    const int z = blockIdx.z;
    const int rowBase = blockIdx.y * 128, colBase = blockIdx.x * 128;

    const uint32_t* AH = z ? kAH : qAH;
    const uint32_t* AL = z ? kAL : qAL;
    const uint32_t* BH = z ? WkH : WqH;
    const uint32_t* BL = z ? WkL : WqL;
    const float* bias = z ? bk : bq;

    float acc[4][8][4];
    gemm_core<3>(sm, sb0, AH, AL, 64, BH, BL, 64,
                 blockIdx.y * 8, blockIdx.x * 16, 64, acc);

    const int lane = threadIdx.x & 31, wid = threadIdx.x >> 5;
    const int warpM = wid & 1, warpN = wid >> 1;
    const int gID = lane >> 2, tig = lane & 3;
#pragma unroll
    for (int mt = 0; mt < 4; mt++) {
        const int r = rowBase + warpM * 64 + mt * 16 + gID;
#pragma unroll
        for (int nt = 0; nt < 8; nt++) {
            const int c = colBase + warpN * 64 + nt * 8 + tig * 2;
            const float b0 = bias[c], b1 = bias[c + 1];
            const float v00 = acc[mt][nt][0] + b0, v01 = acc[mt][nt][1] + b1;
            const float v10 = acc[mt][nt][2] + b0, v11 = acc[mt][nt][3] + b1;
            const int kp = (c & 15) >> 1;
            uint32_t h0, l0, h1, l1;
            f16_split2(v00, v01, h0, l0);
            f16_split2(v10, v11, h1, l1);
            if (z == 0) {   // A-frag planes
                const int lfr = ((r & 7) << 2) | (kp & 3);
                const int rg0 = (kp >> 2) << 1;
                const size_t tb = ((size_t)(r >> 4) * 64 + (c >> 4)) * 128 + lfr * 4 + rg0;
                uint2 uh = {h0, h1}, ul = {l0, l1};
                *(uint2*)(QH + tb) = uh;
                *(uint2*)(QL + tb) = ul;
            } else {        // B-frag planes
                const int lfr = ((r & 7) << 2) | (kp & 3);
                const int rg = kp >> 2;
                const size_t tb0 = ((size_t)(r >> 3) * 64 + (c >> 4)) * 64 + lfr * 2 + rg;
                const size_t tb1 = ((size_t)((r + 8) >> 3) * 64 + (c >> 4)) * 64 + lfr * 2 + rg;
                KH[tb0] = h0; KH[tb1] = h1;
                KL[tb0] = l0; KL[tb1] = l1;
            }
        }
    }
}

// =========================== V projection (1-pass) =========================
__global__ void __launch_bounds__(128, 2) gemm_v(
    const uint32_t* __restrict__ vAH, const uint32_t* __restrict__ WvH,
    const float* __restrict__ bv, uint32_t* __restrict__ Vh)
{
    extern __shared__ uint32_t sm[];
    const uint32_t sb0 = (uint32_t)__cvta_generic_to_shared(sm);
    const int rowBase = blockIdx.y * 128, colBase = blockIdx.x * 128;

    float acc[4][8][4];
    gemm_core<1>(sm, sb0, vAH, nullptr, 64, WvH, nullptr, 64,
                 blockIdx.y * 8, blockIdx.x * 16, 64, acc);

    const int lane = threadIdx.x & 31, wid = threadIdx.x >> 5;
    const int warpM = wid & 1, warpN = wid >> 1;
    const int gID = lane >> 2, tig = lane & 3;
#pragma unroll
    for (int mt = 0; mt < 4; mt++) {
        const int r = rowBase + warpM * 64 + mt * 16 + gID;
#pragma unroll
        for (int nt = 0; nt < 8; nt++) {
            const int c = colBase + warpN * 64 + nt * 8 + tig * 2;
            const float b0 = bv[c], b1 = bv[c + 1];
            Vh[(size_t)r * (MODEL / 2) + (c >> 1)] = f16_pack2(acc[mt][nt][0] + b0, acc[mt][nt][1] + b1);
            Vh[(size_t)(r + 8) * (MODEL / 2) + (c >> 1)] = f16_pack2(acc[mt][nt][2] + b0, acc[mt][nt][3] + b1);
        }
    }
}

// ============================ scores (3-pass) ==============================
__global__ void __launch_bounds__(128, 2) gemm_s(
    const uint32_t* __restrict__ QH, const uint32_t* __restrict__ QL,
    const uint32_t* __restrict__ KH, const uint32_t* __restrict__ KL,
    float* __restrict__ S)
{
    extern __shared__ uint32_t sm[];
    const uint32_t sb0 = (uint32_t)__cvta_generic_to_shared(sm);
    const int z = blockIdx.z;
    const int rowBase = blockIdx.y * 128, colBase = blockIdx.x * 128;
    float* C = S + (size_t)z * SEQ * SEQ;

    float acc[4][8][4];
    gemm_core<3>(sm, sb0, QH, QL, 64, KH, KL, 64,
                 z * 128 + blockIdx.y * 8, z * 256 + blockIdx.x * 16, 64, acc);

    const int lane = threadIdx.x & 31, wid = threadIdx.x >> 5;
    const int warpM = wid & 1, warpN = wid >> 1;
    const int gID = lane >> 2, tig = lane & 3;
#pragma unroll
    for (int mt = 0; mt < 4; mt++) {
        const int r = rowBase + warpM * 64 + mt * 16 + gID;
#pragma unroll
        for (int nt = 0; nt < 8; nt++) {
            const int c = colBase + warpN * 64 + nt * 8 + tig * 2;
            float2 o0 = {acc[mt][nt][0] * 0.03125f, acc[mt][nt][1] * 0.03125f};
            float2 o1 = {acc[mt][nt][2] * 0.03125f, acc[mt][nt][3] * 0.03125f};
            *(float2*)(C + (size_t)r * SEQ + c) = o0;
            *(float2*)(C + (size_t)(r + 8) * SEQ + c) = o1;
        }
    }
}

// =============================== PV (1-pass) ===============================
__global__ void __launch_bounds__(128, 2) gemm_pv(
    const uint32_t* __restrict__ P, const uint32_t* __restrict__ VT,
    float* __restrict__ O)
{
    extern __shared__ uint32_t sm[];
    const uint32_t sb0 = (uint32_t)__cvta_generic_to_shared(sm);
    const int z = blockIdx.z;
    const int rowBase = blockIdx.y * 128, colBase = blockIdx.x * 128;
    float* C = O + (size_t)z * SEQ * MODEL;

    float acc[4][8][4];
    gemm_core<1>(sm, sb0, P, nullptr, SEQ / 16, VT, nullptr, SEQ / 16,
                 z * 128 + blockIdx.y * 8, z * 128 + blockIdx.x * 16, SEQ / 16, acc);

    const int lane = threadIdx.x & 31, wid = threadIdx.x >> 5;
    const int warpM = wid & 1, warpN = wid >> 1;
    const int gID = lane >> 2, tig = lane & 3;
#pragma unroll
    for (int mt = 0; mt < 4; mt++) {
        const int r = rowBase + warpM * 64 + mt * 16 + gID;
#pragma unroll
        for (int nt = 0; nt < 8; nt++) {
            const int c = colBase + warpN * 64 + nt * 8 + tig * 2;
            float2 o0 = {acc[mt][nt][0], acc[mt][nt][1]};
            float2 o1 = {acc[mt][nt][2], acc[mt][nt][3]};
            *(float2*)(C + (size_t)r * MODEL + c) = o0;
            *(float2*)(C + (size_t)(r + 8) * MODEL + c) = o1;
        }
    }
}

// ============ merged pre-splits ============================================
__global__ void split_a3(const float* __restrict__ q, const float* __restrict__ k,
                         const float* __restrict__ v,
                         uint32_t* __restrict__ qAH, uint32_t* __restrict__ qAL,
                         uint32_t* __restrict__ kAH, uint32_t* __restrict__ kAL,
                         uint32_t* __restrict__ vAH) {
    const int z = blockIdx.z;
    const float* X = (z == 0) ? q : (z == 1) ? k : v;
    uint32_t* AH = (z == 0) ? qAH : (z == 1) ? kAH : vAH;
    uint32_t* AL = (z == 0) ? qAL : (z == 1) ? kAL : nullptr;

    const size_t idx = (size_t)blockIdx.x * 256 + threadIdx.x;
    const int r = (int)(idx >> 7);
    const int o = (int)(idx & 127);
    const float4 v0 = ((const float4*)X)[idx * 2];
    const float4 v1 = ((const float4*)X)[idx * 2 + 1];
    const float f[8] = {v0.x, v0.y, v0.z, v0.w, v1.x, v1.y, v1.z, v1.w};
    const size_t tbase = ((size_t)(r >> 4) * (MODEL / 16) + (o >> 1)) * 128;
    const int regr = (r >> 3) & 1;
#pragma unroll
    for (int j = 0; j < 4; j++) {
        const int kp = (o & 1) * 4 + j;
        const int w = (((r & 7) << 2) | (kp & 3)) * 4 + (regr | ((kp >> 2) << 1));
        if (AL) {
            uint32_t hi, lo;
            f16_split2(f[2 * j], f[2 * j + 1], hi, lo);
            AH[tbase + w] = hi;
            AL[tbase + w] = lo;
        } else {
            AH[tbase + w] = f16_pack2(f[2 * j], f[2 * j + 1]);
        }
    }
}

__global__ void split_b3(const float* __restrict__ Wq, const float* __restrict__ Wk,
                         const float* __restrict__ Wv,
                         uint32_t* __restrict__ WqH, uint32_t* __restrict__ WqL,
                         uint32_t* __restrict__ WkH, uint32_t* __restrict__ WkL,
                         uint32_t* __restrict__ WvH) {
    const int z = blockIdx.z;
    const float* W = (z == 0) ? Wq : (z == 1) ? Wk : Wv;
    uint32_t* BH = (z == 0) ? WqH : (z == 1) ? WkH : WvH;
    uint32_t* BL = (z == 0) ? WqL : (z == 1) ? WkL : nullptr;

    __shared__ float s[64][65];
    const int k0 = blockIdx.y * 64, n0 = blockIdx.x * 64;
#pragma unroll
    for (int i = 0; i < 16; i++) {
        const int e = threadIdx.x + i * 256;
        s[e >> 6][e & 63] = W[(size_t)(k0 + (e >> 6)) * MODEL + n0 + (e & 63)];
    }
    __syncthreads();
#pragma unroll
    for (int i = 0; i < 8; i++) {
        const int e = threadIdx.x + i * 256;
        const int n = e >> 5, kp = e & 31;
        const float a = s[kp * 2][n], b = s[kp * 2 + 1][n];
        const int nG = n0 + n;
        const int kp7 = kp & 7;
        const size_t w = ((size_t)(nG >> 3) * (MODEL / 16) + (k0 >> 4) + (kp >> 3)) * 64
                         + (((nG & 7) << 2) | (kp7 & 3)) * 2 + (kp7 >> 2);
        if (BL) {
            uint32_t hi, lo;
            f16_split2(a, b, hi, lo);
            BH[w] = hi;
            BL[w] = lo;
        } else {
            BH[w] = f16_pack2(a, b);
        }
    }
}

// ============ fused softmax (-> P plane) + V -> VT tiles ===================
__global__ void fused_sm_vt(const float* __restrict__ S, uint32_t* __restrict__ P,
                            const uint32_t* __restrict__ Vh, uint32_t* __restrict__ VT) {
    __shared__ float red[8];
    __shared__ uint32_t smv[64][36];

    if (blockIdx.x < MTOT) {
        const int s = blockIdx.x;
        const float* row = S + (size_t)s * SEQ;
        const int tid = threadIdx.x;

        float x[8];
#pragma unroll
        for (int j = 0; j < 4; j++) {
            float2 v = *(const float2*)(row + 2 * (tid + j * 256));
            x[2 * j] = v.x;
            x[2 * j + 1] = v.y;
        }
        float m = x[0];
#pragma unroll
        for (int i = 1; i < 8; i++) m = fmaxf(m, x[i]);
#pragma unroll
        for (int o = 16; o > 0; o >>= 1) m = fmaxf(m, __shfl_xor_sync(0xffffffffu, m, o));
        if ((tid & 31) == 0) red[tid >> 5] = m;
        __syncthreads();
        m = red[0];
#pragma unroll
        for (int i = 1; i < 8; i++) m = fmaxf(m, red[i]);
        __syncthreads();

        float e[8], ssum = 0.0f;
#pragma unroll
        for (int i = 0; i < 8; i++) { e[i] = expf(x[i] - m); ssum += e[i]; }
#pragma unroll
        for (int o = 16; o > 0; o >>= 1) ssum += __shfl_xor_sync(0xffffffffu, ssum, o);
        if ((tid & 31) == 0) red[tid >> 5] = ssum;
        __syncthreads();
        ssum = 0.0f;
#pragma unroll
        for (int i = 0; i < 8; i++) ssum += red[i];
        const float inv = 1.0f / ssum;

        const int laneRow = (s & 7) << 2;
        const int regRow = (s >> 3) & 1;
        const size_t mtOff = (size_t)(s >> 4) * 128;
#pragma unroll
        for (int j = 0; j < 4; j++) {
            const int cp = tid + j * 256;
            const int pl = cp & 7, kt = cp >> 3;
            const int lfr = laneRow | (pl & 3);
            const int rg = regRow | ((pl >> 2) << 1);
            P[(mtOff + kt) * 128 + lfr * 4 + rg] = f16_pack2(e[2 * j] * inv, e[2 * j + 1] * inv);
        }
    } else {
        const int b = blockIdx.x - MTOT;        // 0..2047
        const int z = b >> 9;
        const int t0 = ((b >> 4) & 31) * 64;
        const int d0 = (b & 15) * 64;
        const int tr = threadIdx.x >> 3, dq = threadIdx.x & 7;
#pragma unroll
        for (int i = 0; i < 2; i++) {
            const int t = tr + i * 32;
            *(uint4*)&smv[t][dq * 4] =
                *(const uint4*)(Vh + (size_t)(z * SEQ + t0 + t) * (MODEL / 2) + (d0 >> 1) + dq * 4);
        }
        __syncthreads();
#pragma unroll
        for (int i = 0; i < 8; i++) {
            const int idx = threadIdx.x + i * 256;
            const int tile = idx >> 6, within = idx & 63;
            const int lfr = within >> 1, rg = within & 1;
            const int ntl = tile >> 2, ktl = tile & 3;
            const int n = ntl * 8 + (lfr >> 2);
            const int p = (lfr & 3) | (rg << 2);
            const int k = ktl * 16 + p * 2;
            const uint32_t a = smv[k][n >> 1], bb = smv[k + 1][n >> 1];
            const uint32_t h0 = (n & 1) ? (a >> 16) : (a & 0xffffu);
            const uint32_t h1 = (n & 1) ? (bb >> 16) : (bb & 0xffffu);
            VT[((size_t)(z * 128 + (d0 >> 3) + ntl) * 128 + (t0 >> 4) + ktl) * 64 + within] =
                h0 | (h1 << 16);
        }
    }
}

// ------------------------------- launcher ----------------------------------
extern "C" void kernel_launch(void* const* d_in, const int* in_sizes, int n_in,
                              void* d_out, int out_size) {
    const float* q  = (const float*)d_in[0];
    const float* k  = (const float*)d_in[1];
    const float* v  = (const float*)d_in[2];
    const float* Wq = (const float*)d_in[3];
    const float* Wk = (const float*)d_in[4];
    const float* Wv = (const float*)d_in[5];
    const float* bq = (const float*)d_in[6];
    const float* bk = (const float*)d_in[7];
    const float* bv = (const float*)d_in[8];
    float* out = (float*)d_out;

    uint32_t *qAH, *qAL, *kAH, *kAL, *vAH;
    uint32_t *WqH, *WqL, *WkH, *WkL, *WvH;
    uint32_t *QH, *QL, *KH, *KL, *Vh, *VT, *P;
    float* Sp;
    cudaGetSymbolAddress((void**)&qAH, g_qAH);
    cudaGetSymbolAddress((void**)&qAL, g_qAL);
    cudaGetSymbolAddress((void**)&kAH, g_kAH);
    cudaGetSymbolAddress((void**)&kAL, g_kAL);
    cudaGetSymbolAddress((void**)&vAH, g_vAH);
    cudaGetSymbolAddress((void**)&WqH, g_WqH);
    cudaGetSymbolAddress((void**)&WqL, g_WqL);
    cudaGetSymbolAddress((void**)&WkH, g_WkH);
    cudaGetSymbolAddress((void**)&WkL, g_WkL);
    cudaGetSymbolAddress((void**)&WvH, g_WvH);
    cudaGetSymbolAddress((void**)&QH, g_QH);
    cudaGetSymbolAddress((void**)&QL, g_QL);
    cudaGetSymbolAddress((void**)&KH, g_KH);
    cudaGetSymbolAddress((void**)&KL, g_KL);
    cudaGetSymbolAddress((void**)&Vh, g_Vh);
    cudaGetSymbolAddress((void**)&VT, g_VT);
    cudaGetSymbolAddress((void**)&P,  g_P);
    cudaGetSymbolAddress((void**)&Sp, g_S);

    // pre-splits (merged launches)
    split_a3<<<dim3(4096, 1, 3), 256>>>(q, k, v, qAH, qAL, kAH, kAL, vAH);
    split_b3<<<dim3(16, 16, 3), 256>>>(Wq, Wk, Wv, WqH, WqL, WkH, WkL, WvH);

    // Q + K projections in one launch; V projection
    gemm_qk<<<dim3(8, 64, 2), 128, 49152>>>(qAH, qAL, WqH, WqL, bq, QH, QL,
                                            kAH, kAL, WkH, WkL, bk, KH, KL);
    gemm_v<<<dim3(8, 64, 1), 128, 24576>>>(vAH, WvH, bv, Vh);

    // scores
    gemm_s<<<dim3(16, 16, 4), 128, 49152>>>(QH, QL, KH, KL, Sp);

    // fused softmax (P plane) + V->VT
    fused_sm_vt<<<MTOT + 2048, 256>>>(Sp, P, Vh, VT);

    // O = P V
    gemm_pv<<<dim3(8, 16, 4), 128, 24576>>>(P, VT, out);
}